// round 12
// baseline (speedup 1.0000x reference)
#include <cuda_runtime.h>
#include <cuda_bf16.h>
#include <cstdint>

#define N1 60000
#define N2 50000
#define EDGES 800000
#define DIMV 128
#define NR 16
#define LCN 100
#define KTOT 640
#define P1BLKS 59   // ceil(60000/1024)
#define P2BLKS 49   // ceil(50000/1024)
#define NPBLKS (P1BLKS + P2BLKS)

// ------------------------- scratch (device globals) -------------------------
__device__ float g_xg1[N2 * DIMV];                 // concept-layer output (relu'd), rows < N2
__device__ __nv_bfloat16 g_Ah[N2 * KTOT];          // [x | agg4] hi (bf16)
__device__ __nv_bfloat16 g_Al[N2 * KTOT];          // [x | agg4] lo (bf16)
__device__ float g_xa[N2 * DIMV];                  // rgcn1 output (relu'd)
__device__ __nv_bfloat16 g_xbh[N2 * DIMV];         // rgcn2 output hi
__device__ __nv_bfloat16 g_xbl[N2 * DIMV];         // rgcn2 output lo
__device__ __nv_bfloat16 g_Wh[2 * DIMV * KTOT];    // Wt[n][k] hi, both layers
__device__ __nv_bfloat16 g_Wl[2 * DIMV * KTOT];    // Wt[n][k] lo
__device__ __nv_bfloat16 g_Th[128 * DIMV];         // (ty*w) hi, rows 100..127 zero
__device__ __nv_bfloat16 g_Tl[128 * DIMV];         // (ty*w) lo
__device__ int g_hist1[N1];
__device__ int g_rp1[N1 + 1];
__device__ int g_cur1[N1];
__device__ int g_col1[EDGES];
__device__ int g_rp2[N2 + 1];
__device__ int g_cur2[N2];
__device__ int g_col2[EDGES];                      // packed: src | (etype<<16)
__device__ int g_cseg[N2 * NR];
__device__ int g_part[NPBLKS];
__device__ int g_partsum[NPBLKS];
__device__ int g_scan_ctr;

// --------------------------- packed f32x2 helpers ----------------------------
__device__ __forceinline__ uint64_t pakf(float lo, float hi) {
    uint64_t r;
    asm("mov.b64 %0, {%1, %2};" : "=l"(r)
        : "r"(__float_as_uint(lo)), "r"(__float_as_uint(hi)));
    return r;
}
__device__ __forceinline__ float2 unpak(uint64_t v) {
    uint32_t lo, hi;
    asm("mov.b64 {%0, %1}, %2;" : "=r"(lo), "=r"(hi) : "l"(v));
    return make_float2(__uint_as_float(lo), __uint_as_float(hi));
}
__device__ __forceinline__ void fma2(uint64_t& acc, uint64_t a, uint64_t b) {
    asm("fma.rn.f32x2 %0, %1, %2, %0;" : "+l"(acc) : "l"(a), "l"(b));
}
__device__ __forceinline__ void add2(uint64_t& acc, uint64_t v) {
    asm("add.rn.f32x2 %0, %1, %0;" : "+l"(acc) : "l"(v));
}

// ------------------------------- CSR build ----------------------------------
__global__ void zero_kernel() {
    int i = blockIdx.x * blockDim.x + threadIdx.x;
    if (i == 0) g_scan_ctr = 0;
    if (i < N1) g_hist1[i] = 0;
    if (i < N2 * NR) g_cseg[i] = 0;
}

// 2 edges per thread
__global__ void hist_kernel(const int* __restrict__ ei1,
                            const int* __restrict__ ei2,
                            const int* __restrict__ et2) {
    int i = (blockIdx.x * blockDim.x + threadIdx.x) * 2;
    if (i >= EDGES) return;
    int2 d1 = *(const int2*)(ei1 + EDGES + i);
    atomicAdd(&g_hist1[d1.x], 1);
    atomicAdd(&g_hist1[d1.y], 1);
    int2 d2 = *(const int2*)(ei2 + EDGES + i);
    int2 t2 = *(const int2*)(et2 + i);
    atomicAdd(&g_cseg[d2.x * NR + t2.x], 1);
    atomicAdd(&g_cseg[d2.y * NR + t2.y], 1);
}

// ---- scan: block-local scan (+ fused partials scan in last block) ----------
// graph-2 histogram is derived on the fly from cseg (sum of 16 per node)
__global__ void scan_p1() {
    int b = blockIdx.x;
    int n, base;
    int* rp;
    bool g2 = (b >= P1BLKS);
    if (!g2) { n = N1; base = b << 10; rp = g_rp1; }
    else { n = N2; base = (b - P1BLKS) << 10; rp = g_rp2; }
    int tid = threadIdx.x, lane = tid & 31, wid = tid >> 5;
    __shared__ int wsum[32];
    __shared__ bool is_last;
    int i = base + tid;
    int v = 0;
    if (i < n) {
        if (!g2) {
            v = g_hist1[i];
        } else {
            const int4* cs = (const int4*)(g_cseg + (size_t)i * NR);
            int4 c0 = cs[0], c1 = cs[1], c2 = cs[2], c3 = cs[3];
            v = c0.x + c0.y + c0.z + c0.w + c1.x + c1.y + c1.z + c1.w
              + c2.x + c2.y + c2.z + c2.w + c3.x + c3.y + c3.z + c3.w;
        }
    }
    int inc = v;
    #pragma unroll
    for (int off = 1; off < 32; off <<= 1) {
        int t = __shfl_up_sync(0xFFFFFFFFu, inc, off);
        if (lane >= off) inc += t;
    }
    if (lane == 31) wsum[wid] = inc;
    __syncthreads();
    if (wid == 0) {
        int s = wsum[lane];
        #pragma unroll
        for (int off = 1; off < 32; off <<= 1) {
            int t = __shfl_up_sync(0xFFFFFFFFu, s, off);
            if (lane >= off) s += t;
        }
        wsum[lane] = s;
    }
    __syncthreads();
    int woff = wid ? wsum[wid - 1] : 0;
    if (i < n) rp[i] = woff + inc - v;
    if (tid == 1023) g_part[b] = woff + inc;

    // fused partials scan: last block to finish scans g_part -> g_partsum
    __threadfence();
    if (tid == 0) is_last = (atomicAdd(&g_scan_ctr, 1) == NPBLKS - 1);
    __syncthreads();
    if (is_last && wid < 2) {
        int off2 = wid ? P1BLKS : 0;
        int cnt = wid ? P2BLKS : P1BLKS;
        int carry = 0;
        for (int bb = 0; bb < cnt; bb += 32) {
            int k = bb + lane;
            int vv = (k < cnt) ? g_part[off2 + k] : 0;
            int ic = vv;
            #pragma unroll
            for (int o = 1; o < 32; o <<= 1) {
                int t = __shfl_up_sync(0xFFFFFFFFu, ic, o);
                if (lane >= o) ic += t;
            }
            if (k < cnt) g_partsum[off2 + k] = carry + ic - vv;
            carry += __shfl_sync(0xFFFFFFFFu, ic, 31);
        }
        if (lane == 0) {
            if (wid == 0) g_rp1[N1] = carry;
            else g_rp2[N2] = carry;
        }
    }
}

__global__ void scan_p3() {
    int b = blockIdx.x;
    int n, base;
    int *rp, *cur;
    if (b < P1BLKS) { n = N1; base = b << 10; rp = g_rp1; cur = g_cur1; }
    else { n = N2; base = (b - P1BLKS) << 10; rp = g_rp2; cur = g_cur2; }
    int i = base + threadIdx.x;
    if (i < n) {
        int v = rp[i] + g_partsum[b];
        rp[i] = v;
        cur[i] = v;
    }
}

// 2 edges per thread
__global__ void scatter_kernel(const int* __restrict__ ei1,
                               const int* __restrict__ ei2,
                               const int* __restrict__ et2) {
    int i = (blockIdx.x * blockDim.x + threadIdx.x) * 2;
    if (i >= EDGES) return;
    int2 s1 = *(const int2*)(ei1 + i);
    int2 d1 = *(const int2*)(ei1 + EDGES + i);
    g_col1[atomicAdd(&g_cur1[d1.x], 1)] = s1.x;
    g_col1[atomicAdd(&g_cur1[d1.y], 1)] = s1.y;
    int2 s2 = *(const int2*)(ei2 + i);
    int2 d2 = *(const int2*)(ei2 + EDGES + i);
    int2 t2 = *(const int2*)(et2 + i);
    g_col2[atomicAdd(&g_cur2[d2.x], 1)] = s2.x | (t2.x << 16);
    g_col2[atomicAdd(&g_cur2[d2.y], 1)] = s2.y | (t2.y << 16);
}

// ------------------------------- concept ------------------------------------
// only rows < N2 are materialized; 4 nodes per warp (degree-variance smoothing)
__global__ void concept_kernel(const float4* __restrict__ x) {
    int gw = (blockIdx.x * blockDim.x + threadIdx.x) >> 5;
    int lane = threadIdx.x & 31;
    int n0 = gw * 4;
    #pragma unroll 1
    for (int nn = 0; nn < 4; nn++) {
        int node = n0 + nn;
        if (node >= N2) return;
        int b = g_rp1[node], e = g_rp1[node + 1];
        uint64_t a0 = 0, a1 = 0, b0 = 0, b1 = 0;
        int j = b;
        for (; j + 4 <= e; j += 4) {
            int s0 = g_col1[j], s1 = g_col1[j + 1];
            int s2 = g_col1[j + 2], s3 = g_col1[j + 3];
            float4 x0 = x[s0 * 32 + lane];
            float4 x1 = x[s1 * 32 + lane];
            float4 x2 = x[s2 * 32 + lane];
            float4 x3 = x[s3 * 32 + lane];
            add2(a0, pakf(x0.x, x0.y)); add2(a1, pakf(x0.z, x0.w));
            add2(b0, pakf(x1.x, x1.y)); add2(b1, pakf(x1.z, x1.w));
            add2(a0, pakf(x2.x, x2.y)); add2(a1, pakf(x2.z, x2.w));
            add2(b0, pakf(x3.x, x3.y)); add2(b1, pakf(x3.z, x3.w));
        }
        for (; j < e; j++) {
            float4 x0 = x[g_col1[j] * 32 + lane];
            add2(a0, pakf(x0.x, x0.y)); add2(a1, pakf(x0.z, x0.w));
        }
        add2(a0, b0); add2(a1, b1);
        float2 lo = unpak(a0), hi = unpak(a1);
        float inv = 1.f / (float)max(e - b, 1);
        float4 xv = x[node * 32 + lane];
        float4 r;
        r.x = fmaxf(fmaf(lo.x, inv, xv.x), 0.f);
        r.y = fmaxf(fmaf(lo.y, inv, xv.y), 0.f);
        r.z = fmaxf(fmaf(hi.x, inv, xv.z), 0.f);
        r.w = fmaxf(fmaf(hi.y, inv, xv.w), 0.f);
        ((float4*)g_xg1)[node * 32 + lane] = r;
    }
}

// --------------------------- bf16 split helpers ------------------------------
__device__ __forceinline__ void bsplit(float v, __nv_bfloat16& h, __nv_bfloat16& l) {
    h = __float2bfloat16(v);
    l = __float2bfloat16(v - __bfloat162float(h));
}

__device__ __forceinline__ uint32_t pack2h(float a, float b) {
    __nv_bfloat16 ha, la, hb, lb;
    bsplit(a, ha, la); bsplit(b, hb, lb);
    return (uint32_t)__bfloat16_as_ushort(ha) | ((uint32_t)__bfloat16_as_ushort(hb) << 16);
}
__device__ __forceinline__ uint32_t pack2l(float a, float b) {
    __nv_bfloat16 ha, la, hb, lb;
    bsplit(a, ha, la); bsplit(b, hb, lb);
    return (uint32_t)__bfloat16_as_ushort(la) | ((uint32_t)__bfloat16_as_ushort(lb) << 16);
}

// ------------------------- ty rows: concept(lc) * w --------------------------
__global__ void ty_kernel(const float4* __restrict__ x, const int* __restrict__ lc,
                          const float4* __restrict__ w4) {
    int gw = (blockIdx.x * blockDim.x + threadIdx.x) >> 5;
    if (gw >= 128) return;
    int lane = threadIdx.x & 31;
    uint2 H = make_uint2(0, 0), L = make_uint2(0, 0);
    if (gw < LCN) {
        int v = lc[gw];
        int b = g_rp1[v], e = g_rp1[v + 1];
        float4 acc = make_float4(0.f, 0.f, 0.f, 0.f);
        for (int j = b; j < e; j++) {
            float4 xs = x[g_col1[j] * 32 + lane];
            acc.x += xs.x; acc.y += xs.y; acc.z += xs.z; acc.w += xs.w;
        }
        float inv = 1.f / (float)max(e - b, 1);
        float4 xv = x[v * 32 + lane];
        float4 wv = w4[lane];
        float4 r;
        r.x = fmaxf(fmaf(acc.x, inv, xv.x), 0.f) * wv.x;
        r.y = fmaxf(fmaf(acc.y, inv, xv.y), 0.f) * wv.y;
        r.z = fmaxf(fmaf(acc.z, inv, xv.z), 0.f) * wv.z;
        r.w = fmaxf(fmaf(acc.w, inv, xv.w), 0.f) * wv.w;
        H.x = pack2h(r.x, r.y); H.y = pack2h(r.z, r.w);
        L.x = pack2l(r.x, r.y); L.y = pack2l(r.z, r.w);
    }
    *(uint2*)(g_Th + gw * DIMV + lane * 4) = H;
    *(uint2*)(g_Tl + gw * DIMV + lane * 4) = L;
}

// --------------------------- weights (bf16 split, transposed) ---------------
__global__ void wbuild_kernel(const float* __restrict__ root1, const float* __restrict__ b1,
                              const float* __restrict__ root2, const float* __restrict__ b2) {
    int i = blockIdx.x * blockDim.x + threadIdx.x;
    if (i >= DIMV * KTOT) return;
    int n = i / KTOT, k = i % KTOT;
    float v1 = (k < 128) ? root1[k * 128 + n] : b1[(k - 128) * 128 + n];
    float v2 = (k < 128) ? root2[k * 128 + n] : b2[(k - 128) * 128 + n];
    bsplit(v1, g_Wh[i], g_Wl[i]);
    bsplit(v2, g_Wh[DIMV * KTOT + i], g_Wl[DIMV * KTOT + i]);
}

// --------------------------- RGCN aggregation -------------------------------
__device__ __forceinline__ void split_store2(float2 lo, float2 hi, size_t off) {
    uint2 H, L;
    H.x = pack2h(lo.x, lo.y); H.y = pack2h(hi.x, hi.y);
    L.x = pack2l(lo.x, lo.y); L.y = pack2l(hi.x, hi.y);
    *(uint2*)(g_Ah + off) = H;
    *(uint2*)(g_Al + off) = L;
}

// packed-f32x2 edge update: 4 FMUL + 8 FFMA2 on the fma pipe
__device__ __forceinline__ void agg_fma2(uint64_t* a, float4 c4, float nz, float4 xs) {
    uint64_t xp0 = pakf(xs.x, xs.y), xp1 = pakf(xs.z, xs.w);
    float s0 = c4.x * nz, s1 = c4.y * nz, s2 = c4.z * nz, s3 = c4.w * nz;
    uint64_t c0 = pakf(s0, s0), c1 = pakf(s1, s1);
    uint64_t c2 = pakf(s2, s2), c3 = pakf(s3, s3);
    fma2(a[0], c0, xp0); fma2(a[1], c0, xp1);
    fma2(a[2], c1, xp0); fma2(a[3], c1, xp1);
    fma2(a[4], c2, xp0); fma2(a[5], c2, xp1);
    fma2(a[6], c3, xp0); fma2(a[7], c3, xp1);
}

// 4 nodes per warp (degree-variance smoothing)
__global__ void agg_kernel(int layer, const float* __restrict__ comp) {
    __shared__ float4 comps[NR];
    int tid = threadIdx.x;
    if (tid < NR)
        comps[tid] = make_float4(comp[tid * 4 + 0], comp[tid * 4 + 1],
                                 comp[tid * 4 + 2], comp[tid * 4 + 3]);
    __syncthreads();
    int gw = (blockIdx.x * blockDim.x + tid) >> 5;
    int lane = tid & 31;
    const float4* x = layer ? (const float4*)g_xa : (const float4*)g_xg1;
    int n0 = gw * 4;

    #pragma unroll 1
    for (int nn = 0; nn < 4; nn++) {
        int node = n0 + nn;
        if (node >= N2) return;

        float nrm = 0.f;
        if (lane < NR) nrm = 1.f / (float)max(g_cseg[node * NR + lane], 1);

        int b = g_rp2[node], e = g_rp2[node + 1];
        uint64_t au[8];
        #pragma unroll
        for (int i = 0; i < 8; i++) au[i] = 0;

        int j = b;
        for (; j + 4 <= e; j += 4) {
            int pk0 = g_col2[j], pk1 = g_col2[j + 1];
            int pk2 = g_col2[j + 2], pk3 = g_col2[j + 3];
            int s0 = pk0 & 0xFFFF, t0 = pk0 >> 16;
            int s1 = pk1 & 0xFFFF, t1 = pk1 >> 16;
            int s2 = pk2 & 0xFFFF, t2 = pk2 >> 16;
            int s3 = pk3 & 0xFFFF, t3 = pk3 >> 16;
            float4 x0 = x[s0 * 32 + lane];
            float4 x1 = x[s1 * 32 + lane];
            float4 x2 = x[s2 * 32 + lane];
            float4 x3 = x[s3 * 32 + lane];
            float nz0 = __shfl_sync(0xFFFFFFFFu, nrm, t0);
            float nz1 = __shfl_sync(0xFFFFFFFFu, nrm, t1);
            float nz2 = __shfl_sync(0xFFFFFFFFu, nrm, t2);
            float nz3 = __shfl_sync(0xFFFFFFFFu, nrm, t3);
            agg_fma2(au, comps[t0], nz0, x0);
            agg_fma2(au, comps[t1], nz1, x1);
            agg_fma2(au, comps[t2], nz2, x2);
            agg_fma2(au, comps[t3], nz3, x3);
        }
        for (; j < e; j++) {
            int pk = g_col2[j];
            int s = pk & 0xFFFF, t = pk >> 16;
            float nz = __shfl_sync(0xFFFFFFFFu, nrm, t);
            agg_fma2(au, comps[t], nz, x[s * 32 + lane]);
        }
        size_t base = (size_t)node * KTOT + lane * 4;
        float4 xv = x[node * 32 + lane];
        split_store2(make_float2(xv.x, xv.y), make_float2(xv.z, xv.w), base);
        split_store2(unpak(au[0]), unpak(au[1]), base + 128);
        split_store2(unpak(au[2]), unpak(au[3]), base + 256);
        split_store2(unpak(au[4]), unpak(au[5]), base + 384);
        split_store2(unpak(au[6]), unpak(au[7]), base + 512);
    }
}

// --------------------------- HMMA split-bf16 GEMM ---------------------------
// C[M x 128] = A[M x 640] @ Wt^T + bias   via  Ah*Bh + Ah*Bl + Al*Bh
// 128x128 tile, 256 threads, KC=32, 2-stage cp.async, 2 CTAs/SM (80KB smem)
#define KC 32
#define GSR 40              // bf16 per smem row (stride; conflict-free)
#define GSR4 5              // uint4 per row
#define GSRW 20             // 32-bit words per row
#define GBUF (128 * GSR)    // 5120 bf16 per buffer
#define GBUFB (GBUF * 2)    // 10240 B per buffer
#define GSTGB (4 * GBUFB)   // 40960 B per stage
#define NCHUNK (KTOT / KC)  // 20

__device__ __forceinline__ void mma_bf16(float* c, const uint32_t* a, const uint32_t* b) {
    asm volatile(
        "mma.sync.aligned.m16n8k16.row.col.f32.bf16.bf16.f32 "
        "{%0,%1,%2,%3}, {%4,%5,%6,%7}, {%8,%9}, {%0,%1,%2,%3};"
        : "+f"(c[0]), "+f"(c[1]), "+f"(c[2]), "+f"(c[3])
        : "r"(a[0]), "r"(a[1]), "r"(a[2]), "r"(a[3]), "r"(b[0]), "r"(b[1]));
}

__device__ __forceinline__ void cp16(uint32_t saddr, const void* g, bool pred) {
    int sz = pred ? 16 : 0;
    asm volatile("cp.async.cg.shared.global [%0], [%1], 16, %2;"
                 :: "r"(saddr), "l"(g), "r"(sz));
}

__global__ __launch_bounds__(256, 2) void mma_gemm_kernel(int layer,
                                                          const float* __restrict__ bias,
                                                          int relu) {
    extern __shared__ __nv_bfloat16 sm[];

    const int tid = threadIdx.x;
    const int wid = tid >> 5, lane = tid & 31;
    const int m0 = blockIdx.x * 128;
    const int m0w = (wid >> 2) * 64;
    const int n0w = (wid & 3) * 32;
    const int r = lane >> 2, q = lane & 3;

    const uint4* pAH = (const uint4*)g_Ah;    // 80 uint4 per row
    const uint4* pAL = (const uint4*)g_Al;
    const uint4* pWH = (const uint4*)(g_Wh + (size_t)layer * DIMV * KTOT);
    const uint4* pWL = (const uint4*)(g_Wl + (size_t)layer * DIMV * KTOT);

    uint32_t sbase = (uint32_t)__cvta_generic_to_shared(sm);

    float acc[4][4][4];
    #pragma unroll
    for (int i = 0; i < 4; i++)
        #pragma unroll
        for (int j = 0; j < 4; j++)
            #pragma unroll
            for (int k = 0; k < 4; k++) acc[i][j][k] = 0.f;

    auto stage_load = [&](int c, int s) {
        const int kb = c * 4;               // uint4 col base (KC=32 -> 4 uint4)
        uint32_t st = sbase + (uint32_t)s * GSTGB;
        #pragma unroll
        for (int j = 0; j < 2; j++) {
            int idx = tid + j * 256;
            int row = idx >> 2, col = idx & 3;
            uint32_t so = (uint32_t)(row * GSR4 + col) * 16;
            int m = m0 + row;
            bool ok = m < N2;
            size_t ga = (size_t)(ok ? m : 0) * 80 + kb + col;
            cp16(st + so, pAH + ga, ok);
            cp16(st + GBUFB + so, pAL + ga, ok);
            size_t wo = (size_t)row * 80 + kb + col;
            cp16(st + 2 * GBUFB + so, pWH + wo, true);
            cp16(st + 3 * GBUFB + so, pWL + wo, true);
        }
        asm volatile("cp.async.commit_group;");
    };

    stage_load(0, 0);
    for (int c = 0; c < NCHUNK; c++) {
        if (c < NCHUNK - 1) {
            stage_load(c + 1, (c + 1) & 1);
            asm volatile("cp.async.wait_group 1;");
        } else {
            asm volatile("cp.async.wait_group 0;");
        }
        __syncthreads();

        const __nv_bfloat16* sbuf = sm + (size_t)(c & 1) * (4 * GBUF);
        const uint32_t* Ah32 = (const uint32_t*)sbuf;
        const uint32_t* Al32 = (const uint32_t*)(sbuf + GBUF);
        const uint32_t* Bh32 = (const uint32_t*)(sbuf + 2 * GBUF);
        const uint32_t* Bl32 = (const uint32_t*)(sbuf + 3 * GBUF);

        #pragma unroll
        for (int kk = 0; kk < KC; kk += 16) {
            const int kw = kk >> 1;
            uint32_t ah[4][4], al[4][4], bh[4][2], bl[4][2];
            #pragma unroll
            for (int mt = 0; mt < 4; mt++) {
                int row0 = (m0w + mt * 16 + r) * GSRW;
                int row8 = row0 + 8 * GSRW;
                ah[mt][0] = Ah32[row0 + kw + q];
                ah[mt][1] = Ah32[row8 + kw + q];
                ah[mt][2] = Ah32[row0 + kw + 4 + q];
                ah[mt][3] = Ah32[row8 + kw + 4 + q];
                al[mt][0] = Al32[row0 + kw + q];
                al[mt][1] = Al32[row8 + kw + q];
                al[mt][2] = Al32[row0 + kw + 4 + q];
                al[mt][3] = Al32[row8 + kw + 4 + q];
            }
            #pragma unroll
            for (int nt = 0; nt < 4; nt++) {
                int nrow = (n0w + nt * 8 + r) * GSRW;
                bh[nt][0] = Bh32[nrow + kw + q];
                bh[nt][1] = Bh32[nrow + kw + 4 + q];
                bl[nt][0] = Bl32[nrow + kw + q];
                bl[nt][1] = Bl32[nrow + kw + 4 + q];
            }
            #pragma unroll
            for (int mt = 0; mt < 4; mt++)
                #pragma unroll
                for (int nt = 0; nt < 4; nt++) {
                    mma_bf16(acc[mt][nt], ah[mt], bh[nt]);
                    mma_bf16(acc[mt][nt], ah[mt], bl[nt]);
                    mma_bf16(acc[mt][nt], al[mt], bh[nt]);
                }
        }
        __syncthreads();
    }

    // epilogue: layer 0 -> fp32+relu into g_xa; layer 1 -> bf16 hi/lo split
    #pragma unroll
    for (int nt = 0; nt < 4; nt++) {
        int col = n0w + nt * 8 + q * 2;
        float b0 = bias[col], b1 = bias[col + 1];
        #pragma unroll
        for (int mt = 0; mt < 4; mt++) {
            int row = m0 + m0w + mt * 16 + r;
            float v00 = acc[mt][nt][0] + b0, v01 = acc[mt][nt][1] + b1;
            float v10 = acc[mt][nt][2] + b0, v11 = acc[mt][nt][3] + b1;
            if (relu) {
                v00 = fmaxf(v00, 0.f); v01 = fmaxf(v01, 0.f);
                v10 = fmaxf(v10, 0.f); v11 = fmaxf(v11, 0.f);
            }
            if (layer == 0) {
                if (row < N2)
                    *(float2*)(g_xa + (size_t)row * DIMV + col) = make_float2(v00, v01);
                if (row + 8 < N2)
                    *(float2*)(g_xa + (size_t)(row + 8) * DIMV + col) = make_float2(v10, v11);
            } else {
                if (row < N2) {
                    *(uint32_t*)(g_xbh + (size_t)row * DIMV + col) = pack2h(v00, v01);
                    *(uint32_t*)(g_xbl + (size_t)row * DIMV + col) = pack2l(v00, v01);
                }
                if (row + 8 < N2) {
                    *(uint32_t*)(g_xbh + (size_t)(row + 8) * DIMV + col) = pack2h(v10, v11);
                    *(uint32_t*)(g_xbl + (size_t)(row + 8) * DIMV + col) = pack2l(v10, v11);
                }
            }
        }
    }
}

// ---------------- logits: HMMA split-bf16 GEMM + fused softmax ---------------
#define SROWL 136          // smem row stride in bf16 for K=128 tiles
#define SROWL4 17
#define LBUF (128 * SROWL) // bf16 elems per buffer (17408)
#define LBUFB (LBUF * 2)   // bytes per buffer (34816)

__global__ __launch_bounds__(256, 1) void logits_kernel(float* __restrict__ out) {
    extern __shared__ __nv_bfloat16 sm[];

    const int tid = threadIdx.x;
    const int wid = tid >> 5, lane = tid & 31;
    const int m0 = blockIdx.x * 128;
    const int m0w = (wid >> 2) * 64;
    const int n0w = (wid & 3) * 32;
    const int r = lane >> 2, q = lane & 3;

    uint32_t sbase = (uint32_t)__cvta_generic_to_shared(sm);

    const uint4* pAH = (const uint4*)g_xbh;   // 16 uint4 per row
    const uint4* pAL = (const uint4*)g_xbl;
    const uint4* pTH = (const uint4*)g_Th;
    const uint4* pTL = (const uint4*)g_Tl;
    #pragma unroll
    for (int j = 0; j < 8; j++) {
        int idx = tid + j * 256;
        int row = idx >> 4, col = idx & 15;
        uint32_t so = (uint32_t)(row * SROWL4 + col) * 16;
        int m = m0 + row;
        bool ok = m < N2;
        size_t ga = (size_t)(ok ? m : 0) * 16 + col;
        cp16(sbase + so, pAH + ga, ok);
        cp16(sbase + LBUFB + so, pAL + ga, ok);
        size_t ta = (size_t)row * 16 + col;
        cp16(sbase + 2 * LBUFB + so, pTH + ta, true);
        cp16(sbase + 3 * LBUFB + so, pTL + ta, true);
    }
    asm volatile("cp.async.commit_group;");
    asm volatile("cp.async.wait_group 0;");
    __syncthreads();

    float acc[4][4][4];
    #pragma unroll
    for (int i = 0; i < 4; i++)
        #pragma unroll
        for (int j = 0; j < 4; j++)
            #pragma unroll
            for (int k = 0; k < 4; k++) acc[i][j][k] = 0.f;

    const uint32_t* Ah32 = (const uint32_t*)sm;
    const uint32_t* Al32 = (const uint32_t*)(sm + LBUF);
    const uint32_t* Bh32 = (const uint32_t*)(sm + 2 * LBUF);
    const uint32_t* Bl32 = (const uint32_t*)(sm + 3 * LBUF);

    #pragma unroll
    for (int kk = 0; kk < 128; kk += 16) {
        const int kw = kk >> 1;
        uint32_t ah[4][4], al[4][4], bh[4][2], bl[4][2];
        #pragma unroll
        for (int mt = 0; mt < 4; mt++) {
            int row0 = (m0w + mt * 16 + r) * (SROWL / 2);
            int row8 = row0 + 8 * (SROWL / 2);
            ah[mt][0] = Ah32[row0 + kw + q];
            ah[mt][1] = Ah32[row8 + kw + q];
            ah[mt][2] = Ah32[row0 + kw + 4 + q];
            ah[mt][3] = Ah32[row8 + kw + 4 + q];
            al[mt][0] = Al32[row0 + kw + q];
            al[mt][1] = Al32[row8 + kw + q];
            al[mt][2] = Al32[row0 + kw + 4 + q];
            al[mt][3] = Al32[row8 + kw + 4 + q];
        }
        #pragma unroll
        for (int nt = 0; nt < 4; nt++) {
            int nrow = (n0w + nt * 8 + r) * (SROWL / 2);
            bh[nt][0] = Bh32[nrow + kw + q];
            bh[nt][1] = Bh32[nrow + kw + 4 + q];
            bl[nt][0] = Bl32[nrow + kw + q];
            bl[nt][1] = Bl32[nrow + kw + 4 + q];
        }
        #pragma unroll
        for (int mt = 0; mt < 4; mt++)
            #pragma unroll
            for (int nt = 0; nt < 4; nt++) {
                mma_bf16(acc[mt][nt], ah[mt], bh[nt]);
                mma_bf16(acc[mt][nt], ah[mt], bl[nt]);
                mma_bf16(acc[mt][nt], al[mt], bh[nt]);
            }
    }
    __syncthreads();

    // dump logits to smem (reuse staging region), stride 104 floats
    float* LS = (float*)sm;
    #pragma unroll
    for (int nt = 0; nt < 4; nt++) {
        int col = n0w + nt * 8 + q * 2;
        if (col < LCN) {
            #pragma unroll
            for (int mt = 0; mt < 4; mt++) {
                int row = m0w + mt * 16 + r;
                LS[row * 104 + col] = acc[mt][nt][0];
                LS[row * 104 + col + 1] = acc[mt][nt][1];
                LS[(row + 8) * 104 + col] = acc[mt][nt][2];
                LS[(row + 8) * 104 + col + 1] = acc[mt][nt][3];
            }
        }
    }
    __syncthreads();

    // softmax: each warp handles 16 rows
    #pragma unroll 1
    for (int i = 0; i < 16; i++) {
        int row = wid * 16 + i;
        int grow = m0 + row;
        float d0 = LS[row * 104 + lane];
        float d1 = LS[row * 104 + lane + 32];
        float d2 = LS[row * 104 + lane + 64];
        float d3 = (lane < 4) ? LS[row * 104 + lane + 96] : -1e30f;
        float mx = fmaxf(fmaxf(d0, d1), fmaxf(d2, d3));
        #pragma unroll
        for (int off = 16; off > 0; off >>= 1)
            mx = fmaxf(mx, __shfl_xor_sync(0xFFFFFFFFu, mx, off));
        float e0 = expf(d0 - mx), e1 = expf(d1 - mx), e2 = expf(d2 - mx);
        float e3 = (lane < 4) ? expf(d3 - mx) : 0.f;
        float s = e0 + e1 + e2 + e3;
        #pragma unroll
        for (int off = 16; off > 0; off >>= 1)
            s += __shfl_xor_sync(0xFFFFFFFFu, s, off);
        float inv = 1.f / s;
        if (grow < N2) {
            float* orow = out + (size_t)grow * LCN;
            orow[lane] = e0 * inv;
            orow[lane + 32] = e1 * inv;
            orow[lane + 64] = e2 * inv;
            if (lane < 4) orow[lane + 96] = e3 * inv;
        }
    }
}

// ------------------------------- launcher -----------------------------------
extern "C" void kernel_launch(void* const* d_in, const int* in_sizes, int n_in,
                              void* d_out, int out_size) {
    const int* ei2 = (const int*)d_in[0];
    const int* et2 = (const int*)d_in[1];
    const int* ei1 = (const int*)d_in[2];
    const int* lc  = (const int*)d_in[3];
    const float* x0     = (const float*)d_in[4];
    const float* basis1 = (const float*)d_in[5];
    const float* comp1  = (const float*)d_in[6];
    const float* root1  = (const float*)d_in[7];
    const float* bias1  = (const float*)d_in[8];
    const float* basis2 = (const float*)d_in[9];
    const float* comp2  = (const float*)d_in[10];
    const float* root2  = (const float*)d_in[11];
    const float* bias2  = (const float*)d_in[12];
    const float* w      = (const float*)d_in[13];
    float* out = (float*)d_out;

    const int GEMM_SMEM = 2 * GSTGB;           // 81920 (2 stages, 2 CTAs/SM)
    cudaFuncSetAttribute(mma_gemm_kernel, cudaFuncAttributeMaxDynamicSharedMemorySize,
                         GEMM_SMEM);
    const int LOGITS_SMEM = 4 * LBUFB;         // 139264
    cudaFuncSetAttribute(logits_kernel, cudaFuncAttributeMaxDynamicSharedMemorySize,
                         LOGITS_SMEM);

    zero_kernel<<<(N2 * NR + 255) / 256, 256>>>();
    hist_kernel<<<(EDGES / 2 + 255) / 256, 256>>>(ei1, ei2, et2);
    scan_p1<<<NPBLKS, 1024>>>();
    scan_p3<<<NPBLKS, 1024>>>();
    scatter_kernel<<<(EDGES / 2 + 255) / 256, 256>>>(ei1, ei2, et2);
    concept_kernel<<<(N2 + 31) / 32, 256>>>((const float4*)x0);
    ty_kernel<<<16, 256>>>((const float4*)x0, lc, (const float4*)w);
    wbuild_kernel<<<(DIMV * KTOT + 255) / 256, 256>>>(root1, basis1, root2, basis2);

    agg_kernel<<<(N2 + 31) / 32, 256>>>(0, comp1);
    mma_gemm_kernel<<<(N2 + 127) / 128, 256, GEMM_SMEM>>>(0, bias1, 1);
    agg_kernel<<<(N2 + 31) / 32, 256>>>(1, comp2);
    mma_gemm_kernel<<<(N2 + 127) / 128, 256, GEMM_SMEM>>>(1, bias2, 0);

    logits_kernel<<<(N2 + 127) / 128, 256, LOGITS_SMEM>>>(out);
}

// round 13
// speedup vs baseline: 1.0170x; 1.0170x over previous
#include <cuda_runtime.h>
#include <cuda_bf16.h>
#include <cstdint>

#define N1 60000
#define N2 50000
#define EDGES 800000
#define DIMV 128
#define NR 16
#define LCN 100
#define KTOT 640
#define P1BLKS 59   // ceil(60000/1024)
#define P2BLKS 49   // ceil(50000/1024)
#define NPBLKS (P1BLKS + P2BLKS)

// ------------------------- scratch (device globals) -------------------------
__device__ float g_xg1[N2 * DIMV];                 // concept-layer output (relu'd), rows < N2
__device__ __nv_bfloat16 g_Ah[N2 * KTOT];          // [x | agg4] hi (bf16)
__device__ __nv_bfloat16 g_Al[N2 * KTOT];          // [x | agg4] lo (bf16)
__device__ float g_xa[N2 * DIMV];                  // rgcn1 output (relu'd)
__device__ __nv_bfloat16 g_xbh[N2 * DIMV];         // rgcn2 output hi
__device__ __nv_bfloat16 g_xbl[N2 * DIMV];         // rgcn2 output lo
__device__ __nv_bfloat16 g_Wh[2 * DIMV * KTOT];    // Wt[n][k] hi, both layers
__device__ __nv_bfloat16 g_Wl[2 * DIMV * KTOT];    // Wt[n][k] lo
__device__ __nv_bfloat16 g_Th[128 * DIMV];         // (ty*w) hi, rows 100..127 zero
__device__ __nv_bfloat16 g_Tl[128 * DIMV];         // (ty*w) lo
__device__ int g_hist1[N1];
__device__ int g_rp1[N1 + 1];
__device__ int g_cur1[N1];
__device__ int g_col1[EDGES];
__device__ int g_rp2[N2 + 1];
__device__ int g_cur2[N2];
__device__ int g_col2[EDGES];                      // packed: src | (etype<<16)
__device__ int g_cseg[N2 * NR];
__device__ int g_part[NPBLKS];
__device__ int g_partsum[NPBLKS];
__device__ int g_scan_ctr;

// --------------------------- packed f32x2 helpers ----------------------------
__device__ __forceinline__ uint64_t pakf(float lo, float hi) {
    uint64_t r;
    asm("mov.b64 %0, {%1, %2};" : "=l"(r)
        : "r"(__float_as_uint(lo)), "r"(__float_as_uint(hi)));
    return r;
}
__device__ __forceinline__ float2 unpak(uint64_t v) {
    uint32_t lo, hi;
    asm("mov.b64 {%0, %1}, %2;" : "=r"(lo), "=r"(hi) : "l"(v));
    return make_float2(__uint_as_float(lo), __uint_as_float(hi));
}
__device__ __forceinline__ void fma2(uint64_t& acc, uint64_t a, uint64_t b) {
    asm("fma.rn.f32x2 %0, %1, %2, %0;" : "+l"(acc) : "l"(a), "l"(b));
}
__device__ __forceinline__ void add2(uint64_t& acc, uint64_t v) {
    asm("add.rn.f32x2 %0, %1, %0;" : "+l"(acc) : "l"(v));
}

// ------------------------------- CSR build ----------------------------------
__global__ void zero_kernel() {
    int i = blockIdx.x * blockDim.x + threadIdx.x;
    if (i == 0) g_scan_ctr = 0;
    if (i < N1) g_hist1[i] = 0;
    if (i < N2 * NR) g_cseg[i] = 0;
}

// 2 edges per thread
__global__ void hist_kernel(const int* __restrict__ ei1,
                            const int* __restrict__ ei2,
                            const int* __restrict__ et2) {
    int i = (blockIdx.x * blockDim.x + threadIdx.x) * 2;
    if (i >= EDGES) return;
    int2 d1 = *(const int2*)(ei1 + EDGES + i);
    atomicAdd(&g_hist1[d1.x], 1);
    atomicAdd(&g_hist1[d1.y], 1);
    int2 d2 = *(const int2*)(ei2 + EDGES + i);
    int2 t2 = *(const int2*)(et2 + i);
    atomicAdd(&g_cseg[d2.x * NR + t2.x], 1);
    atomicAdd(&g_cseg[d2.y * NR + t2.y], 1);
}

// ---- scan: block-local scan (+ fused partials scan in last block) ----------
// graph-2 histogram is derived on the fly from cseg (sum of 16 per node)
__global__ void scan_p1() {
    int b = blockIdx.x;
    int n, base;
    int* rp;
    bool g2 = (b >= P1BLKS);
    if (!g2) { n = N1; base = b << 10; rp = g_rp1; }
    else { n = N2; base = (b - P1BLKS) << 10; rp = g_rp2; }
    int tid = threadIdx.x, lane = tid & 31, wid = tid >> 5;
    __shared__ int wsum[32];
    __shared__ bool is_last;
    int i = base + tid;
    int v = 0;
    if (i < n) {
        if (!g2) {
            v = g_hist1[i];
        } else {
            const int4* cs = (const int4*)(g_cseg + (size_t)i * NR);
            int4 c0 = cs[0], c1 = cs[1], c2 = cs[2], c3 = cs[3];
            v = c0.x + c0.y + c0.z + c0.w + c1.x + c1.y + c1.z + c1.w
              + c2.x + c2.y + c2.z + c2.w + c3.x + c3.y + c3.z + c3.w;
        }
    }
    int inc = v;
    #pragma unroll
    for (int off = 1; off < 32; off <<= 1) {
        int t = __shfl_up_sync(0xFFFFFFFFu, inc, off);
        if (lane >= off) inc += t;
    }
    if (lane == 31) wsum[wid] = inc;
    __syncthreads();
    if (wid == 0) {
        int s = wsum[lane];
        #pragma unroll
        for (int off = 1; off < 32; off <<= 1) {
            int t = __shfl_up_sync(0xFFFFFFFFu, s, off);
            if (lane >= off) s += t;
        }
        wsum[lane] = s;
    }
    __syncthreads();
    int woff = wid ? wsum[wid - 1] : 0;
    if (i < n) rp[i] = woff + inc - v;
    if (tid == 1023) g_part[b] = woff + inc;

    // fused partials scan: last block to finish scans g_part -> g_partsum
    __threadfence();
    if (tid == 0) is_last = (atomicAdd(&g_scan_ctr, 1) == NPBLKS - 1);
    __syncthreads();
    if (is_last && wid < 2) {
        int off2 = wid ? P1BLKS : 0;
        int cnt = wid ? P2BLKS : P1BLKS;
        int carry = 0;
        for (int bb = 0; bb < cnt; bb += 32) {
            int k = bb + lane;
            int vv = (k < cnt) ? g_part[off2 + k] : 0;
            int ic = vv;
            #pragma unroll
            for (int o = 1; o < 32; o <<= 1) {
                int t = __shfl_up_sync(0xFFFFFFFFu, ic, o);
                if (lane >= o) ic += t;
            }
            if (k < cnt) g_partsum[off2 + k] = carry + ic - vv;
            carry += __shfl_sync(0xFFFFFFFFu, ic, 31);
        }
        if (lane == 0) {
            if (wid == 0) g_rp1[N1] = carry;
            else g_rp2[N2] = carry;
        }
    }
}

__global__ void scan_p3() {
    int b = blockIdx.x;
    int n, base;
    int *rp, *cur;
    if (b < P1BLKS) { n = N1; base = b << 10; rp = g_rp1; cur = g_cur1; }
    else { n = N2; base = (b - P1BLKS) << 10; rp = g_rp2; cur = g_cur2; }
    int i = base + threadIdx.x;
    if (i < n) {
        int v = rp[i] + g_partsum[b];
        rp[i] = v;
        cur[i] = v;
    }
}

// 2 edges per thread
__global__ void scatter_kernel(const int* __restrict__ ei1,
                               const int* __restrict__ ei2,
                               const int* __restrict__ et2) {
    int i = (blockIdx.x * blockDim.x + threadIdx.x) * 2;
    if (i >= EDGES) return;
    int2 s1 = *(const int2*)(ei1 + i);
    int2 d1 = *(const int2*)(ei1 + EDGES + i);
    g_col1[atomicAdd(&g_cur1[d1.x], 1)] = s1.x;
    g_col1[atomicAdd(&g_cur1[d1.y], 1)] = s1.y;
    int2 s2 = *(const int2*)(ei2 + i);
    int2 d2 = *(const int2*)(ei2 + EDGES + i);
    int2 t2 = *(const int2*)(et2 + i);
    g_col2[atomicAdd(&g_cur2[d2.x], 1)] = s2.x | (t2.x << 16);
    g_col2[atomicAdd(&g_cur2[d2.y], 1)] = s2.y | (t2.y << 16);
}

// ------------------------------- concept ------------------------------------
// only rows < N2 are materialized; 4 nodes per warp (degree-variance smoothing)
__global__ void concept_kernel(const float4* __restrict__ x) {
    int gw = (blockIdx.x * blockDim.x + threadIdx.x) >> 5;
    int lane = threadIdx.x & 31;
    int n0 = gw * 4;
    #pragma unroll 1
    for (int nn = 0; nn < 4; nn++) {
        int node = n0 + nn;
        if (node >= N2) return;
        int b = g_rp1[node], e = g_rp1[node + 1];
        uint64_t a0 = 0, a1 = 0, b0 = 0, b1 = 0;
        int j = b;
        for (; j + 4 <= e; j += 4) {
            int s0 = g_col1[j], s1 = g_col1[j + 1];
            int s2 = g_col1[j + 2], s3 = g_col1[j + 3];
            float4 x0 = x[s0 * 32 + lane];
            float4 x1 = x[s1 * 32 + lane];
            float4 x2 = x[s2 * 32 + lane];
            float4 x3 = x[s3 * 32 + lane];
            add2(a0, pakf(x0.x, x0.y)); add2(a1, pakf(x0.z, x0.w));
            add2(b0, pakf(x1.x, x1.y)); add2(b1, pakf(x1.z, x1.w));
            add2(a0, pakf(x2.x, x2.y)); add2(a1, pakf(x2.z, x2.w));
            add2(b0, pakf(x3.x, x3.y)); add2(b1, pakf(x3.z, x3.w));
        }
        for (; j < e; j++) {
            float4 x0 = x[g_col1[j] * 32 + lane];
            add2(a0, pakf(x0.x, x0.y)); add2(a1, pakf(x0.z, x0.w));
        }
        add2(a0, b0); add2(a1, b1);
        float2 lo = unpak(a0), hi = unpak(a1);
        float inv = 1.f / (float)max(e - b, 1);
        float4 xv = x[node * 32 + lane];
        float4 r;
        r.x = fmaxf(fmaf(lo.x, inv, xv.x), 0.f);
        r.y = fmaxf(fmaf(lo.y, inv, xv.y), 0.f);
        r.z = fmaxf(fmaf(hi.x, inv, xv.z), 0.f);
        r.w = fmaxf(fmaf(hi.y, inv, xv.w), 0.f);
        ((float4*)g_xg1)[node * 32 + lane] = r;
    }
}

// --------------------------- bf16 split helpers ------------------------------
__device__ __forceinline__ void bsplit(float v, __nv_bfloat16& h, __nv_bfloat16& l) {
    h = __float2bfloat16(v);
    l = __float2bfloat16(v - __bfloat162float(h));
}

__device__ __forceinline__ uint32_t pack2h(float a, float b) {
    __nv_bfloat16 ha, la, hb, lb;
    bsplit(a, ha, la); bsplit(b, hb, lb);
    return (uint32_t)__bfloat16_as_ushort(ha) | ((uint32_t)__bfloat16_as_ushort(hb) << 16);
}
__device__ __forceinline__ uint32_t pack2l(float a, float b) {
    __nv_bfloat16 ha, la, hb, lb;
    bsplit(a, ha, la); bsplit(b, hb, lb);
    return (uint32_t)__bfloat16_as_ushort(la) | ((uint32_t)__bfloat16_as_ushort(lb) << 16);
}

// ------------------------- ty rows: concept(lc) * w --------------------------
__global__ void ty_kernel(const float4* __restrict__ x, const int* __restrict__ lc,
                          const float4* __restrict__ w4) {
    int gw = (blockIdx.x * blockDim.x + threadIdx.x) >> 5;
    if (gw >= 128) return;
    int lane = threadIdx.x & 31;
    uint2 H = make_uint2(0, 0), L = make_uint2(0, 0);
    if (gw < LCN) {
        int v = lc[gw];
        int b = g_rp1[v], e = g_rp1[v + 1];
        float4 acc = make_float4(0.f, 0.f, 0.f, 0.f);
        for (int j = b; j < e; j++) {
            float4 xs = x[g_col1[j] * 32 + lane];
            acc.x += xs.x; acc.y += xs.y; acc.z += xs.z; acc.w += xs.w;
        }
        float inv = 1.f / (float)max(e - b, 1);
        float4 xv = x[v * 32 + lane];
        float4 wv = w4[lane];
        float4 r;
        r.x = fmaxf(fmaf(acc.x, inv, xv.x), 0.f) * wv.x;
        r.y = fmaxf(fmaf(acc.y, inv, xv.y), 0.f) * wv.y;
        r.z = fmaxf(fmaf(acc.z, inv, xv.z), 0.f) * wv.z;
        r.w = fmaxf(fmaf(acc.w, inv, xv.w), 0.f) * wv.w;
        H.x = pack2h(r.x, r.y); H.y = pack2h(r.z, r.w);
        L.x = pack2l(r.x, r.y); L.y = pack2l(r.z, r.w);
    }
    *(uint2*)(g_Th + gw * DIMV + lane * 4) = H;
    *(uint2*)(g_Tl + gw * DIMV + lane * 4) = L;
}

// --------------------------- weights (bf16 split, transposed) ---------------
__global__ void wbuild_kernel(const float* __restrict__ root1, const float* __restrict__ b1,
                              const float* __restrict__ root2, const float* __restrict__ b2) {
    int i = blockIdx.x * blockDim.x + threadIdx.x;
    if (i >= DIMV * KTOT) return;
    int n = i / KTOT, k = i % KTOT;
    float v1 = (k < 128) ? root1[k * 128 + n] : b1[(k - 128) * 128 + n];
    float v2 = (k < 128) ? root2[k * 128 + n] : b2[(k - 128) * 128 + n];
    bsplit(v1, g_Wh[i], g_Wl[i]);
    bsplit(v2, g_Wh[DIMV * KTOT + i], g_Wl[DIMV * KTOT + i]);
}

// --------------------------- RGCN aggregation -------------------------------
__device__ __forceinline__ void split_store2(float2 lo, float2 hi, size_t off) {
    uint2 H, L;
    H.x = pack2h(lo.x, lo.y); H.y = pack2h(hi.x, hi.y);
    L.x = pack2l(lo.x, lo.y); L.y = pack2l(hi.x, hi.y);
    *(uint2*)(g_Ah + off) = H;
    *(uint2*)(g_Al + off) = L;
}

// packed-f32x2 edge update: 4 FMUL + 8 FFMA2 on the fma pipe
__device__ __forceinline__ void agg_fma2(uint64_t* a, float4 c4, float nz, float4 xs) {
    uint64_t xp0 = pakf(xs.x, xs.y), xp1 = pakf(xs.z, xs.w);
    float s0 = c4.x * nz, s1 = c4.y * nz, s2 = c4.z * nz, s3 = c4.w * nz;
    uint64_t c0 = pakf(s0, s0), c1 = pakf(s1, s1);
    uint64_t c2 = pakf(s2, s2), c3 = pakf(s3, s3);
    fma2(a[0], c0, xp0); fma2(a[1], c0, xp1);
    fma2(a[2], c1, xp0); fma2(a[3], c1, xp1);
    fma2(a[4], c2, xp0); fma2(a[5], c2, xp1);
    fma2(a[6], c3, xp0); fma2(a[7], c3, xp1);
}

// 4 nodes per warp (degree-variance smoothing)
__global__ void agg_kernel(int layer, const float* __restrict__ comp) {
    __shared__ float4 comps[NR];
    int tid = threadIdx.x;
    if (tid < NR)
        comps[tid] = make_float4(comp[tid * 4 + 0], comp[tid * 4 + 1],
                                 comp[tid * 4 + 2], comp[tid * 4 + 3]);
    __syncthreads();
    int gw = (blockIdx.x * blockDim.x + tid) >> 5;
    int lane = tid & 31;
    const float4* x = layer ? (const float4*)g_xa : (const float4*)g_xg1;
    int n0 = gw * 4;

    #pragma unroll 1
    for (int nn = 0; nn < 4; nn++) {
        int node = n0 + nn;
        if (node >= N2) return;

        float nrm = 0.f;
        if (lane < NR) nrm = 1.f / (float)max(g_cseg[node * NR + lane], 1);

        int b = g_rp2[node], e = g_rp2[node + 1];
        uint64_t au[8];
        #pragma unroll
        for (int i = 0; i < 8; i++) au[i] = 0;

        int j = b;
        for (; j + 4 <= e; j += 4) {
            int pk0 = g_col2[j], pk1 = g_col2[j + 1];
            int pk2 = g_col2[j + 2], pk3 = g_col2[j + 3];
            int s0 = pk0 & 0xFFFF, t0 = pk0 >> 16;
            int s1 = pk1 & 0xFFFF, t1 = pk1 >> 16;
            int s2 = pk2 & 0xFFFF, t2 = pk2 >> 16;
            int s3 = pk3 & 0xFFFF, t3 = pk3 >> 16;
            float4 x0 = x[s0 * 32 + lane];
            float4 x1 = x[s1 * 32 + lane];
            float4 x2 = x[s2 * 32 + lane];
            float4 x3 = x[s3 * 32 + lane];
            float nz0 = __shfl_sync(0xFFFFFFFFu, nrm, t0);
            float nz1 = __shfl_sync(0xFFFFFFFFu, nrm, t1);
            float nz2 = __shfl_sync(0xFFFFFFFFu, nrm, t2);
            float nz3 = __shfl_sync(0xFFFFFFFFu, nrm, t3);
            agg_fma2(au, comps[t0], nz0, x0);
            agg_fma2(au, comps[t1], nz1, x1);
            agg_fma2(au, comps[t2], nz2, x2);
            agg_fma2(au, comps[t3], nz3, x3);
        }
        for (; j < e; j++) {
            int pk = g_col2[j];
            int s = pk & 0xFFFF, t = pk >> 16;
            float nz = __shfl_sync(0xFFFFFFFFu, nrm, t);
            agg_fma2(au, comps[t], nz, x[s * 32 + lane]);
        }
        size_t base = (size_t)node * KTOT + lane * 4;
        float4 xv = x[node * 32 + lane];
        split_store2(make_float2(xv.x, xv.y), make_float2(xv.z, xv.w), base);
        split_store2(unpak(au[0]), unpak(au[1]), base + 128);
        split_store2(unpak(au[2]), unpak(au[3]), base + 256);
        split_store2(unpak(au[4]), unpak(au[5]), base + 384);
        split_store2(unpak(au[6]), unpak(au[7]), base + 512);
    }
}

// --------------------------- HMMA split-bf16 GEMM ---------------------------
// C[M x 128] = A[M x 640] @ Wt^T + bias   via  Ah*Bh + Ah*Bl + Al*Bh
// 128x128 tile, 256 threads, KC=64, 2-stage cp.async, ldmatrix fragment loads
#define KC 64
#define SROW 72
#define SROWB 144            // bytes per smem row
#define SROW4 9
#define SBUF (128 * SROW)
#define STGB (4 * SBUF * 2)
#define BUFB (SBUF * 2)

__device__ __forceinline__ void mma_bf16(float* c, const uint32_t* a, const uint32_t* b) {
    asm volatile(
        "mma.sync.aligned.m16n8k16.row.col.f32.bf16.bf16.f32 "
        "{%0,%1,%2,%3}, {%4,%5,%6,%7}, {%8,%9}, {%0,%1,%2,%3};"
        : "+f"(c[0]), "+f"(c[1]), "+f"(c[2]), "+f"(c[3])
        : "r"(a[0]), "r"(a[1]), "r"(a[2]), "r"(a[3]), "r"(b[0]), "r"(b[1]));
}

#define LDSM4(r, a) \
    asm volatile("ldmatrix.sync.aligned.m8n8.x4.shared.b16 {%0,%1,%2,%3}, [%4];" \
        : "=r"((r)[0]), "=r"((r)[1]), "=r"((r)[2]), "=r"((r)[3]) : "r"(a))

__device__ __forceinline__ void cp16(uint32_t saddr, const void* g, bool pred) {
    int sz = pred ? 16 : 0;
    asm volatile("cp.async.cg.shared.global [%0], [%1], 16, %2;"
                 :: "r"(saddr), "l"(g), "r"(sz));
}

__global__ __launch_bounds__(256, 1) void mma_gemm_kernel(int layer,
                                                          const float* __restrict__ bias,
                                                          int relu) {
    extern __shared__ __nv_bfloat16 sm[];

    const int tid = threadIdx.x;
    const int wid = tid >> 5, lane = tid & 31;
    const int m0 = blockIdx.x * 128;
    const int m0w = (wid >> 2) * 64;
    const int n0w = (wid & 3) * 32;
    const int r = lane >> 2, q = lane & 3;

    const uint4* pAH = (const uint4*)g_Ah;
    const uint4* pAL = (const uint4*)g_Al;
    const uint4* pWH = (const uint4*)(g_Wh + (size_t)layer * DIMV * KTOT);
    const uint4* pWL = (const uint4*)(g_Wl + (size_t)layer * DIMV * KTOT);

    uint32_t sbase = (uint32_t)__cvta_generic_to_shared(sm);

    // per-thread ldmatrix offsets within a plane (bytes)
    // A (m16k16, x4): lanes 0-7 rows0-7/k0, 8-15 rows8-15/k0, 16-23 rows0-7/k8, 24-31 rows8-15/k8
    uint32_t aoff[4];
    #pragma unroll
    for (int mt = 0; mt < 4; mt++)
        aoff[mt] = (uint32_t)(m0w + mt * 16 + (lane & 15)) * SROWB + ((lane >> 4) << 4);
    // B (two n8k16 fragments per x4): tile = lane>>3; nt-in-pair = (lane>>4)&1; k8 = (lane>>3)&1
    uint32_t boff[2];
    #pragma unroll
    for (int p = 0; p < 2; p++)
        boff[p] = (uint32_t)(n0w + (2 * p + ((lane >> 4) & 1)) * 8 + (lane & 7)) * SROWB
                  + (((lane >> 3) & 1) << 4);

    float acc[4][4][4];
    #pragma unroll
    for (int i = 0; i < 4; i++)
        #pragma unroll
        for (int j = 0; j < 4; j++)
            #pragma unroll
            for (int k = 0; k < 4; k++) acc[i][j][k] = 0.f;

    auto stage_load = [&](int c, int s) {
        const int kb = c * 8;
        uint32_t st = sbase + (uint32_t)s * STGB;
        #pragma unroll
        for (int j = 0; j < 4; j++) {
            int idx = tid + j * 256;
            int row = idx >> 3, col = idx & 7;
            uint32_t so = (uint32_t)(row * SROW4 + col) * 16;
            int m = m0 + row;
            bool ok = m < N2;
            size_t ga = (size_t)(ok ? m : 0) * 80 + kb + col;
            cp16(st + so, pAH + ga, ok);
            cp16(st + BUFB + so, pAL + ga, ok);
            size_t wo = (size_t)row * 80 + kb + col;
            cp16(st + 2 * BUFB + so, pWH + wo, true);
            cp16(st + 3 * BUFB + so, pWL + wo, true);
        }
        asm volatile("cp.async.commit_group;");
    };

    stage_load(0, 0);
    for (int c = 0; c < KTOT / KC; c++) {
        if (c < KTOT / KC - 1) {
            stage_load(c + 1, (c + 1) & 1);
            asm volatile("cp.async.wait_group 1;");
        } else {
            asm volatile("cp.async.wait_group 0;");
        }
        __syncthreads();

        uint32_t bufb = sbase + (uint32_t)(c & 1) * STGB;

        #pragma unroll
        for (int kk = 0; kk < KC; kk += 16) {
            const uint32_t kbyte = (uint32_t)kk * 2;
            uint32_t ah[4][4], al[4][4], bhl[2][4], bll[2][4];
            #pragma unroll
            for (int mt = 0; mt < 4; mt++) {
                LDSM4(ah[mt], bufb + aoff[mt] + kbyte);
                LDSM4(al[mt], bufb + BUFB + aoff[mt] + kbyte);
            }
            #pragma unroll
            for (int p = 0; p < 2; p++) {
                LDSM4(bhl[p], bufb + 2 * BUFB + boff[p] + kbyte);
                LDSM4(bll[p], bufb + 3 * BUFB + boff[p] + kbyte);
            }
            #pragma unroll
            for (int mt = 0; mt < 4; mt++)
                #pragma unroll
                for (int nt = 0; nt < 4; nt++) {
                    const uint32_t* bh = &bhl[nt >> 1][(nt & 1) * 2];
                    const uint32_t* bl = &bll[nt >> 1][(nt & 1) * 2];
                    mma_bf16(acc[mt][nt], ah[mt], bh);
                    mma_bf16(acc[mt][nt], ah[mt], bl);
                    mma_bf16(acc[mt][nt], al[mt], bh);
                }
        }
        __syncthreads();
    }

    // epilogue: layer 0 -> fp32+relu into g_xa; layer 1 -> bf16 hi/lo split
    #pragma unroll
    for (int nt = 0; nt < 4; nt++) {
        int col = n0w + nt * 8 + q * 2;
        float b0 = bias[col], b1 = bias[col + 1];
        #pragma unroll
        for (int mt = 0; mt < 4; mt++) {
            int row = m0 + m0w + mt * 16 + r;
            float v00 = acc[mt][nt][0] + b0, v01 = acc[mt][nt][1] + b1;
            float v10 = acc[mt][nt][2] + b0, v11 = acc[mt][nt][3] + b1;
            if (relu) {
                v00 = fmaxf(v00, 0.f); v01 = fmaxf(v01, 0.f);
                v10 = fmaxf(v10, 0.f); v11 = fmaxf(v11, 0.f);
            }
            if (layer == 0) {
                if (row < N2)
                    *(float2*)(g_xa + (size_t)row * DIMV + col) = make_float2(v00, v01);
                if (row + 8 < N2)
                    *(float2*)(g_xa + (size_t)(row + 8) * DIMV + col) = make_float2(v10, v11);
            } else {
                if (row < N2) {
                    *(uint32_t*)(g_xbh + (size_t)row * DIMV + col) = pack2h(v00, v01);
                    *(uint32_t*)(g_xbl + (size_t)row * DIMV + col) = pack2l(v00, v01);
                }
                if (row + 8 < N2) {
                    *(uint32_t*)(g_xbh + (size_t)(row + 8) * DIMV + col) = pack2h(v10, v11);
                    *(uint32_t*)(g_xbl + (size_t)(row + 8) * DIMV + col) = pack2l(v10, v11);
                }
            }
        }
    }
}

// ---------------- logits: HMMA split-bf16 GEMM + fused softmax ---------------
#define SROWL 136          // smem row stride in bf16 for K=128 tiles
#define SROWL4 17
#define LBUF (128 * SROWL) // bf16 elems per buffer (17408)
#define LBUFB (LBUF * 2)   // bytes per buffer (34816)

__global__ __launch_bounds__(256, 1) void logits_kernel(float* __restrict__ out) {
    extern __shared__ __nv_bfloat16 sm[];

    const int tid = threadIdx.x;
    const int wid = tid >> 5, lane = tid & 31;
    const int m0 = blockIdx.x * 128;
    const int m0w = (wid >> 2) * 64;
    const int n0w = (wid & 3) * 32;
    const int r = lane >> 2, q = lane & 3;

    uint32_t sbase = (uint32_t)__cvta_generic_to_shared(sm);

    const uint4* pAH = (const uint4*)g_xbh;   // 16 uint4 per row
    const uint4* pAL = (const uint4*)g_xbl;
    const uint4* pTH = (const uint4*)g_Th;
    const uint4* pTL = (const uint4*)g_Tl;
    #pragma unroll
    for (int j = 0; j < 8; j++) {
        int idx = tid + j * 256;
        int row = idx >> 4, col = idx & 15;
        uint32_t so = (uint32_t)(row * SROWL4 + col) * 16;
        int m = m0 + row;
        bool ok = m < N2;
        size_t ga = (size_t)(ok ? m : 0) * 16 + col;
        cp16(sbase + so, pAH + ga, ok);
        cp16(sbase + LBUFB + so, pAL + ga, ok);
        size_t ta = (size_t)row * 16 + col;
        cp16(sbase + 2 * LBUFB + so, pTH + ta, true);
        cp16(sbase + 3 * LBUFB + so, pTL + ta, true);
    }
    asm volatile("cp.async.commit_group;");
    asm volatile("cp.async.wait_group 0;");
    __syncthreads();

    float acc[4][4][4];
    #pragma unroll
    for (int i = 0; i < 4; i++)
        #pragma unroll
        for (int j = 0; j < 4; j++)
            #pragma unroll
            for (int k = 0; k < 4; k++) acc[i][j][k] = 0.f;

    const uint32_t* Ah32 = (const uint32_t*)sm;
    const uint32_t* Al32 = (const uint32_t*)(sm + LBUF);
    const uint32_t* Bh32 = (const uint32_t*)(sm + 2 * LBUF);
    const uint32_t* Bl32 = (const uint32_t*)(sm + 3 * LBUF);

    #pragma unroll
    for (int kk = 0; kk < 128; kk += 16) {
        const int kw = kk >> 1;
        uint32_t ah[4][4], al[4][4], bh[4][2], bl[4][2];
        #pragma unroll
        for (int mt = 0; mt < 4; mt++) {
            int row0 = (m0w + mt * 16 + r) * (SROWL / 2);
            int row8 = row0 + 8 * (SROWL / 2);
            ah[mt][0] = Ah32[row0 + kw + q];
            ah[mt][1] = Ah32[row8 + kw + q];
            ah[mt][2] = Ah32[row0 + kw + 4 + q];
            ah[mt][3] = Ah32[row8 + kw + 4 + q];
            al[mt][0] = Al32[row0 + kw + q];
            al[mt][1] = Al32[row8 + kw + q];
            al[mt][2] = Al32[row0 + kw + 4 + q];
            al[mt][3] = Al32[row8 + kw + 4 + q];
        }
        #pragma unroll
        for (int nt = 0; nt < 4; nt++) {
            int nrow = (n0w + nt * 8 + r) * (SROWL / 2);
            bh[nt][0] = Bh32[nrow + kw + q];
            bh[nt][1] = Bh32[nrow + kw + 4 + q];
            bl[nt][0] = Bl32[nrow + kw + q];
            bl[nt][1] = Bl32[nrow + kw + 4 + q];
        }
        #pragma unroll
        for (int mt = 0; mt < 4; mt++)
            #pragma unroll
            for (int nt = 0; nt < 4; nt++) {
                mma_bf16(acc[mt][nt], ah[mt], bh[nt]);
                mma_bf16(acc[mt][nt], ah[mt], bl[nt]);
                mma_bf16(acc[mt][nt], al[mt], bh[nt]);
            }
    }
    __syncthreads();

    // dump logits to smem (reuse staging region), stride 104 floats
    float* LS = (float*)sm;
    #pragma unroll
    for (int nt = 0; nt < 4; nt++) {
        int col = n0w + nt * 8 + q * 2;
        if (col < LCN) {
            #pragma unroll
            for (int mt = 0; mt < 4; mt++) {
                int row = m0w + mt * 16 + r;
                LS[row * 104 + col] = acc[mt][nt][0];
                LS[row * 104 + col + 1] = acc[mt][nt][1];
                LS[(row + 8) * 104 + col] = acc[mt][nt][2];
                LS[(row + 8) * 104 + col + 1] = acc[mt][nt][3];
            }
        }
    }
    __syncthreads();

    // softmax: each warp handles 16 rows
    #pragma unroll 1
    for (int i = 0; i < 16; i++) {
        int row = wid * 16 + i;
        int grow = m0 + row;
        float d0 = LS[row * 104 + lane];
        float d1 = LS[row * 104 + lane + 32];
        float d2 = LS[row * 104 + lane + 64];
        float d3 = (lane < 4) ? LS[row * 104 + lane + 96] : -1e30f;
        float mx = fmaxf(fmaxf(d0, d1), fmaxf(d2, d3));
        #pragma unroll
        for (int off = 16; off > 0; off >>= 1)
            mx = fmaxf(mx, __shfl_xor_sync(0xFFFFFFFFu, mx, off));
        float e0 = expf(d0 - mx), e1 = expf(d1 - mx), e2 = expf(d2 - mx);
        float e3 = (lane < 4) ? expf(d3 - mx) : 0.f;
        float s = e0 + e1 + e2 + e3;
        #pragma unroll
        for (int off = 16; off > 0; off >>= 1)
            s += __shfl_xor_sync(0xFFFFFFFFu, s, off);
        float inv = 1.f / s;
        if (grow < N2) {
            float* orow = out + (size_t)grow * LCN;
            orow[lane] = e0 * inv;
            orow[lane + 32] = e1 * inv;
            orow[lane + 64] = e2 * inv;
            if (lane < 4) orow[lane + 96] = e3 * inv;
        }
    }
}

// ------------------------------- launcher -----------------------------------
extern "C" void kernel_launch(void* const* d_in, const int* in_sizes, int n_in,
                              void* d_out, int out_size) {
    const int* ei2 = (const int*)d_in[0];
    const int* et2 = (const int*)d_in[1];
    const int* ei1 = (const int*)d_in[2];
    const int* lc  = (const int*)d_in[3];
    const float* x0     = (const float*)d_in[4];
    const float* basis1 = (const float*)d_in[5];
    const float* comp1  = (const float*)d_in[6];
    const float* root1  = (const float*)d_in[7];
    const float* bias1  = (const float*)d_in[8];
    const float* basis2 = (const float*)d_in[9];
    const float* comp2  = (const float*)d_in[10];
    const float* root2  = (const float*)d_in[11];
    const float* bias2  = (const float*)d_in[12];
    const float* w      = (const float*)d_in[13];
    float* out = (float*)d_out;

    const int GEMM_SMEM = 2 * STGB;            // 147456 (2 stages)
    cudaFuncSetAttribute(mma_gemm_kernel, cudaFuncAttributeMaxDynamicSharedMemorySize,
                         GEMM_SMEM);
    const int LOGITS_SMEM = 4 * LBUFB;         // 139264
    cudaFuncSetAttribute(logits_kernel, cudaFuncAttributeMaxDynamicSharedMemorySize,
                         LOGITS_SMEM);

    zero_kernel<<<(N2 * NR + 255) / 256, 256>>>();
    hist_kernel<<<(EDGES / 2 + 255) / 256, 256>>>(ei1, ei2, et2);
    scan_p1<<<NPBLKS, 1024>>>();
    scan_p3<<<NPBLKS, 1024>>>();
    scatter_kernel<<<(EDGES / 2 + 255) / 256, 256>>>(ei1, ei2, et2);
    concept_kernel<<<(N2 + 31) / 32, 256>>>((const float4*)x0);
    ty_kernel<<<16, 256>>>((const float4*)x0, lc, (const float4*)w);
    wbuild_kernel<<<(DIMV * KTOT + 255) / 256, 256>>>(root1, basis1, root2, basis2);

    agg_kernel<<<(N2 + 31) / 32, 256>>>(0, comp1);
    mma_gemm_kernel<<<(N2 + 127) / 128, 256, GEMM_SMEM>>>(0, bias1, 1);
    agg_kernel<<<(N2 + 31) / 32, 256>>>(1, comp2);
    mma_gemm_kernel<<<(N2 + 127) / 128, 256, GEMM_SMEM>>>(1, bias2, 0);

    logits_kernel<<<(N2 + 127) / 128, 256, LOGITS_SMEM>>>(out);
}

// round 14
// speedup vs baseline: 1.0255x; 1.0084x over previous
#include <cuda_runtime.h>
#include <cuda_bf16.h>
#include <cstdint>

#define N1 60000
#define N2 50000
#define EDGES 800000
#define DIMV 128
#define NR 16
#define LCN 100
#define KTOT 640
#define P1BLKS 59   // ceil(60000/1024)
#define P2BLKS 49   // ceil(50000/1024)
#define NPBLKS (P1BLKS + P2BLKS)

// ------------------------- scratch (device globals) -------------------------
__device__ float g_xg1[N2 * DIMV];                 // concept-layer output (relu'd), rows < N2
__device__ __nv_bfloat16 g_Ah[N2 * KTOT];          // [x | agg4] hi (bf16)
__device__ __nv_bfloat16 g_Al[N2 * KTOT];          // [x | agg4] lo (bf16)
__device__ float g_xa[N2 * DIMV];                  // rgcn1 output (relu'd)
__device__ __nv_bfloat16 g_xbh[N2 * DIMV];         // rgcn2 output hi
__device__ __nv_bfloat16 g_xbl[N2 * DIMV];         // rgcn2 output lo
__device__ __nv_bfloat16 g_Wh[2 * DIMV * KTOT];    // Wt[n][k] hi, both layers
__device__ __nv_bfloat16 g_Wl[2 * DIMV * KTOT];    // Wt[n][k] lo
__device__ __nv_bfloat16 g_Th[128 * DIMV];         // (ty*w) hi, rows 100..127 zero
__device__ __nv_bfloat16 g_Tl[128 * DIMV];         // (ty*w) lo
__device__ int g_hist1[N1];
__device__ int g_rp1[N1 + 1];
__device__ int g_cur1[N1];
__device__ int g_col1[EDGES];
__device__ int g_rp2[N2 + 1];
__device__ int g_cur2[N2];
__device__ int g_col2[EDGES];                      // packed: src | (etype<<16)
__device__ int g_cseg[N2 * NR];
__device__ int g_part[NPBLKS];
__device__ int g_partsum[NPBLKS];
__device__ int g_ctrA, g_ctrB;

// --------------------------- packed f32x2 helpers ----------------------------
__device__ __forceinline__ uint64_t pakf(float lo, float hi) {
    uint64_t r;
    asm("mov.b64 %0, {%1, %2};" : "=l"(r)
        : "r"(__float_as_uint(lo)), "r"(__float_as_uint(hi)));
    return r;
}
__device__ __forceinline__ float2 unpak(uint64_t v) {
    uint32_t lo, hi;
    asm("mov.b64 {%0, %1}, %2;" : "=r"(lo), "=r"(hi) : "l"(v));
    return make_float2(__uint_as_float(lo), __uint_as_float(hi));
}
__device__ __forceinline__ void fma2(uint64_t& acc, uint64_t a, uint64_t b) {
    asm("fma.rn.f32x2 %0, %1, %2, %0;" : "+l"(acc) : "l"(a), "l"(b));
}
__device__ __forceinline__ void add2(uint64_t& acc, uint64_t v) {
    asm("add.rn.f32x2 %0, %1, %0;" : "+l"(acc) : "l"(v));
}

// ------------------------------- CSR build (per-graph) ----------------------
__global__ void zero1_kernel() {
    int i = blockIdx.x * blockDim.x + threadIdx.x;
    if (i == 0) g_ctrA = 0;
    if (i < N1) g_hist1[i] = 0;
}
__global__ void zero2_kernel() {
    int i = blockIdx.x * blockDim.x + threadIdx.x;
    if (i == 0) g_ctrB = 0;
    if (i < N2 * NR) g_cseg[i] = 0;
}

__global__ void hist1_kernel(const int* __restrict__ ei1) {
    int i = (blockIdx.x * blockDim.x + threadIdx.x) * 2;
    if (i >= EDGES) return;
    int2 d1 = *(const int2*)(ei1 + EDGES + i);
    atomicAdd(&g_hist1[d1.x], 1);
    atomicAdd(&g_hist1[d1.y], 1);
}
__global__ void hist2_kernel(const int* __restrict__ ei2, const int* __restrict__ et2) {
    int i = (blockIdx.x * blockDim.x + threadIdx.x) * 2;
    if (i >= EDGES) return;
    int2 d2 = *(const int2*)(ei2 + EDGES + i);
    int2 t2 = *(const int2*)(et2 + i);
    atomicAdd(&g_cseg[d2.x * NR + t2.x], 1);
    atomicAdd(&g_cseg[d2.y * NR + t2.y], 1);
}

// block-local scan + fused partials scan in last-finishing block (per graph)
__device__ __forceinline__ void scan_body(int b, int n, int base, const int* srcval,
                                          int* rp, int* ctr, int poff, int pcnt,
                                          int* totdst) {
    int tid = threadIdx.x, lane = tid & 31, wid = tid >> 5;
    __shared__ int wsum[32];
    __shared__ bool is_last;
    int i = base + tid;
    int v = (i < n) ? srcval[tid] : 0;   // srcval is per-thread value already
    (void)v;
    int inc = v;
    #pragma unroll
    for (int off = 1; off < 32; off <<= 1) {
        int t = __shfl_up_sync(0xFFFFFFFFu, inc, off);
        if (lane >= off) inc += t;
    }
    if (lane == 31) wsum[wid] = inc;
    __syncthreads();
    if (wid == 0) {
        int s = wsum[lane];
        #pragma unroll
        for (int off = 1; off < 32; off <<= 1) {
            int t = __shfl_up_sync(0xFFFFFFFFu, s, off);
            if (lane >= off) s += t;
        }
        wsum[lane] = s;
    }
    __syncthreads();
    int woff = wid ? wsum[wid - 1] : 0;
    if (i < n) rp[i] = woff + inc - v;
    if (tid == 1023) g_part[poff + b] = woff + inc;

    __threadfence();
    if (tid == 0) is_last = (atomicAdd(ctr, 1) == pcnt - 1);
    __syncthreads();
    if (is_last && wid == 0) {
        int carry = 0;
        for (int bb = 0; bb < pcnt; bb += 32) {
            int k = bb + lane;
            int vv = (k < pcnt) ? g_part[poff + k] : 0;
            int ic = vv;
            #pragma unroll
            for (int o = 1; o < 32; o <<= 1) {
                int t = __shfl_up_sync(0xFFFFFFFFu, ic, o);
                if (lane >= o) ic += t;
            }
            if (k < pcnt) g_partsum[poff + k] = carry + ic - vv;
            carry += __shfl_sync(0xFFFFFFFFu, ic, 31);
        }
        if (lane == 0) *totdst = carry;
    }
}

__global__ void scan_g1() {
    int b = blockIdx.x;
    int base = b << 10;
    int i = base + threadIdx.x;
    int v = (i < N1) ? g_hist1[i] : 0;
    __shared__ int sval[1024];
    sval[threadIdx.x] = v;
    __syncthreads();
    scan_body(b, N1, base, sval, g_rp1, &g_ctrA, 0, P1BLKS, &g_rp1[N1]);
}

__global__ void scan_g2() {
    int b = blockIdx.x;
    int base = b << 10;
    int i = base + threadIdx.x;
    int v = 0;
    if (i < N2) {
        const int4* cs = (const int4*)(g_cseg + (size_t)i * NR);
        int4 c0 = cs[0], c1 = cs[1], c2 = cs[2], c3 = cs[3];
        v = c0.x + c0.y + c0.z + c0.w + c1.x + c1.y + c1.z + c1.w
          + c2.x + c2.y + c2.z + c2.w + c3.x + c3.y + c3.z + c3.w;
    }
    __shared__ int sval[1024];
    sval[threadIdx.x] = v;
    __syncthreads();
    scan_body(b, N2, base, sval, g_rp2, &g_ctrB, P1BLKS, P2BLKS, &g_rp2[N2]);
}

__global__ void scan_add1() {
    int b = blockIdx.x;
    int i = (b << 10) + threadIdx.x;
    if (i < N1) {
        int v = g_rp1[i] + g_partsum[b];
        g_rp1[i] = v;
        g_cur1[i] = v;
    }
}
__global__ void scan_add2() {
    int b = blockIdx.x;
    int i = (b << 10) + threadIdx.x;
    if (i < N2) {
        int v = g_rp2[i] + g_partsum[P1BLKS + b];
        g_rp2[i] = v;
        g_cur2[i] = v;
    }
}

__global__ void scatter1_kernel(const int* __restrict__ ei1) {
    int i = (blockIdx.x * blockDim.x + threadIdx.x) * 2;
    if (i >= EDGES) return;
    int2 s1 = *(const int2*)(ei1 + i);
    int2 d1 = *(const int2*)(ei1 + EDGES + i);
    g_col1[atomicAdd(&g_cur1[d1.x], 1)] = s1.x;
    g_col1[atomicAdd(&g_cur1[d1.y], 1)] = s1.y;
}
__global__ void scatter2_kernel(const int* __restrict__ ei2, const int* __restrict__ et2) {
    int i = (blockIdx.x * blockDim.x + threadIdx.x) * 2;
    if (i >= EDGES) return;
    int2 s2 = *(const int2*)(ei2 + i);
    int2 d2 = *(const int2*)(ei2 + EDGES + i);
    int2 t2 = *(const int2*)(et2 + i);
    g_col2[atomicAdd(&g_cur2[d2.x], 1)] = s2.x | (t2.x << 16);
    g_col2[atomicAdd(&g_cur2[d2.y], 1)] = s2.y | (t2.y << 16);
}

// ------------------------------- concept ------------------------------------
// only rows < N2 are materialized; 4 nodes per warp (degree-variance smoothing)
__global__ void concept_kernel(const float4* __restrict__ x) {
    int gw = (blockIdx.x * blockDim.x + threadIdx.x) >> 5;
    int lane = threadIdx.x & 31;
    int n0 = gw * 4;
    #pragma unroll 1
    for (int nn = 0; nn < 4; nn++) {
        int node = n0 + nn;
        if (node >= N2) return;
        int b = g_rp1[node], e = g_rp1[node + 1];
        uint64_t a0 = 0, a1 = 0, b0 = 0, b1 = 0;
        int j = b;
        for (; j + 4 <= e; j += 4) {
            int s0 = g_col1[j], s1 = g_col1[j + 1];
            int s2 = g_col1[j + 2], s3 = g_col1[j + 3];
            float4 x0 = x[s0 * 32 + lane];
            float4 x1 = x[s1 * 32 + lane];
            float4 x2 = x[s2 * 32 + lane];
            float4 x3 = x[s3 * 32 + lane];
            add2(a0, pakf(x0.x, x0.y)); add2(a1, pakf(x0.z, x0.w));
            add2(b0, pakf(x1.x, x1.y)); add2(b1, pakf(x1.z, x1.w));
            add2(a0, pakf(x2.x, x2.y)); add2(a1, pakf(x2.z, x2.w));
            add2(b0, pakf(x3.x, x3.y)); add2(b1, pakf(x3.z, x3.w));
        }
        for (; j < e; j++) {
            float4 x0 = x[g_col1[j] * 32 + lane];
            add2(a0, pakf(x0.x, x0.y)); add2(a1, pakf(x0.z, x0.w));
        }
        add2(a0, b0); add2(a1, b1);
        float2 lo = unpak(a0), hi = unpak(a1);
        float inv = 1.f / (float)max(e - b, 1);
        float4 xv = x[node * 32 + lane];
        float4 r;
        r.x = fmaxf(fmaf(lo.x, inv, xv.x), 0.f);
        r.y = fmaxf(fmaf(lo.y, inv, xv.y), 0.f);
        r.z = fmaxf(fmaf(hi.x, inv, xv.z), 0.f);
        r.w = fmaxf(fmaf(hi.y, inv, xv.w), 0.f);
        ((float4*)g_xg1)[node * 32 + lane] = r;
    }
}

// --------------------------- bf16 split helpers ------------------------------
__device__ __forceinline__ void bsplit(float v, __nv_bfloat16& h, __nv_bfloat16& l) {
    h = __float2bfloat16(v);
    l = __float2bfloat16(v - __bfloat162float(h));
}

__device__ __forceinline__ uint32_t pack2h(float a, float b) {
    __nv_bfloat16 ha, la, hb, lb;
    bsplit(a, ha, la); bsplit(b, hb, lb);
    return (uint32_t)__bfloat16_as_ushort(ha) | ((uint32_t)__bfloat16_as_ushort(hb) << 16);
}
__device__ __forceinline__ uint32_t pack2l(float a, float b) {
    __nv_bfloat16 ha, la, hb, lb;
    bsplit(a, ha, la); bsplit(b, hb, lb);
    return (uint32_t)__bfloat16_as_ushort(la) | ((uint32_t)__bfloat16_as_ushort(lb) << 16);
}

// ------------------------- ty rows: concept(lc) * w --------------------------
__global__ void ty_kernel(const float4* __restrict__ x, const int* __restrict__ lc,
                          const float4* __restrict__ w4) {
    int gw = (blockIdx.x * blockDim.x + threadIdx.x) >> 5;
    if (gw >= 128) return;
    int lane = threadIdx.x & 31;
    uint2 H = make_uint2(0, 0), L = make_uint2(0, 0);
    if (gw < LCN) {
        int v = lc[gw];
        int b = g_rp1[v], e = g_rp1[v + 1];
        float4 acc = make_float4(0.f, 0.f, 0.f, 0.f);
        for (int j = b; j < e; j++) {
            float4 xs = x[g_col1[j] * 32 + lane];
            acc.x += xs.x; acc.y += xs.y; acc.z += xs.z; acc.w += xs.w;
        }
        float inv = 1.f / (float)max(e - b, 1);
        float4 xv = x[v * 32 + lane];
        float4 wv = w4[lane];
        float4 r;
        r.x = fmaxf(fmaf(acc.x, inv, xv.x), 0.f) * wv.x;
        r.y = fmaxf(fmaf(acc.y, inv, xv.y), 0.f) * wv.y;
        r.z = fmaxf(fmaf(acc.z, inv, xv.z), 0.f) * wv.z;
        r.w = fmaxf(fmaf(acc.w, inv, xv.w), 0.f) * wv.w;
        H.x = pack2h(r.x, r.y); H.y = pack2h(r.z, r.w);
        L.x = pack2l(r.x, r.y); L.y = pack2l(r.z, r.w);
    }
    *(uint2*)(g_Th + gw * DIMV + lane * 4) = H;
    *(uint2*)(g_Tl + gw * DIMV + lane * 4) = L;
}

// --------------------------- weights (bf16 split, transposed) ---------------
__global__ void wbuild_kernel(const float* __restrict__ root1, const float* __restrict__ b1,
                              const float* __restrict__ root2, const float* __restrict__ b2) {
    int i = blockIdx.x * blockDim.x + threadIdx.x;
    if (i >= DIMV * KTOT) return;
    int n = i / KTOT, k = i % KTOT;
    float v1 = (k < 128) ? root1[k * 128 + n] : b1[(k - 128) * 128 + n];
    float v2 = (k < 128) ? root2[k * 128 + n] : b2[(k - 128) * 128 + n];
    bsplit(v1, g_Wh[i], g_Wl[i]);
    bsplit(v2, g_Wh[DIMV * KTOT + i], g_Wl[DIMV * KTOT + i]);
}

// --------------------------- RGCN aggregation -------------------------------
__device__ __forceinline__ void split_store2(float2 lo, float2 hi, size_t off) {
    uint2 H, L;
    H.x = pack2h(lo.x, lo.y); H.y = pack2h(hi.x, hi.y);
    L.x = pack2l(lo.x, lo.y); L.y = pack2l(hi.x, hi.y);
    *(uint2*)(g_Ah + off) = H;
    *(uint2*)(g_Al + off) = L;
}

// packed-f32x2 edge update: 4 FMUL + 8 FFMA2 on the fma pipe
__device__ __forceinline__ void agg_fma2(uint64_t* a, float4 c4, float nz, float4 xs) {
    uint64_t xp0 = pakf(xs.x, xs.y), xp1 = pakf(xs.z, xs.w);
    float s0 = c4.x * nz, s1 = c4.y * nz, s2 = c4.z * nz, s3 = c4.w * nz;
    uint64_t c0 = pakf(s0, s0), c1 = pakf(s1, s1);
    uint64_t c2 = pakf(s2, s2), c3 = pakf(s3, s3);
    fma2(a[0], c0, xp0); fma2(a[1], c0, xp1);
    fma2(a[2], c1, xp0); fma2(a[3], c1, xp1);
    fma2(a[4], c2, xp0); fma2(a[5], c2, xp1);
    fma2(a[6], c3, xp0); fma2(a[7], c3, xp1);
}

// 4 nodes per warp (degree-variance smoothing)
__global__ void agg_kernel(int layer, const float* __restrict__ comp) {
    __shared__ float4 comps[NR];
    int tid = threadIdx.x;
    if (tid < NR)
        comps[tid] = make_float4(comp[tid * 4 + 0], comp[tid * 4 + 1],
                                 comp[tid * 4 + 2], comp[tid * 4 + 3]);
    __syncthreads();
    int gw = (blockIdx.x * blockDim.x + tid) >> 5;
    int lane = tid & 31;
    const float4* x = layer ? (const float4*)g_xa : (const float4*)g_xg1;
    int n0 = gw * 4;

    #pragma unroll 1
    for (int nn = 0; nn < 4; nn++) {
        int node = n0 + nn;
        if (node >= N2) return;

        float nrm = 0.f;
        if (lane < NR) nrm = 1.f / (float)max(g_cseg[node * NR + lane], 1);

        int b = g_rp2[node], e = g_rp2[node + 1];
        uint64_t au[8];
        #pragma unroll
        for (int i = 0; i < 8; i++) au[i] = 0;

        int j = b;
        for (; j + 4 <= e; j += 4) {
            int pk0 = g_col2[j], pk1 = g_col2[j + 1];
            int pk2 = g_col2[j + 2], pk3 = g_col2[j + 3];
            int s0 = pk0 & 0xFFFF, t0 = pk0 >> 16;
            int s1 = pk1 & 0xFFFF, t1 = pk1 >> 16;
            int s2 = pk2 & 0xFFFF, t2 = pk2 >> 16;
            int s3 = pk3 & 0xFFFF, t3 = pk3 >> 16;
            float4 x0 = x[s0 * 32 + lane];
            float4 x1 = x[s1 * 32 + lane];
            float4 x2 = x[s2 * 32 + lane];
            float4 x3 = x[s3 * 32 + lane];
            float nz0 = __shfl_sync(0xFFFFFFFFu, nrm, t0);
            float nz1 = __shfl_sync(0xFFFFFFFFu, nrm, t1);
            float nz2 = __shfl_sync(0xFFFFFFFFu, nrm, t2);
            float nz3 = __shfl_sync(0xFFFFFFFFu, nrm, t3);
            agg_fma2(au, comps[t0], nz0, x0);
            agg_fma2(au, comps[t1], nz1, x1);
            agg_fma2(au, comps[t2], nz2, x2);
            agg_fma2(au, comps[t3], nz3, x3);
        }
        for (; j < e; j++) {
            int pk = g_col2[j];
            int s = pk & 0xFFFF, t = pk >> 16;
            float nz = __shfl_sync(0xFFFFFFFFu, nrm, t);
            agg_fma2(au, comps[t], nz, x[s * 32 + lane]);
        }
        size_t base = (size_t)node * KTOT + lane * 4;
        float4 xv = x[node * 32 + lane];
        split_store2(make_float2(xv.x, xv.y), make_float2(xv.z, xv.w), base);
        split_store2(unpak(au[0]), unpak(au[1]), base + 128);
        split_store2(unpak(au[2]), unpak(au[3]), base + 256);
        split_store2(unpak(au[4]), unpak(au[5]), base + 384);
        split_store2(unpak(au[6]), unpak(au[7]), base + 512);
    }
}

// --------------------------- HMMA split-bf16 GEMM ---------------------------
// C[M x 128] = A[M x 640] @ Wt^T + bias   via  Ah*Bh + Ah*Bl + Al*Bh
// 128x128 tile, 256 threads, KC=64, 2-stage cp.async, ldmatrix fragment loads
#define KC 64
#define SROW 72
#define SROWB 144            // bytes per smem row
#define SROW4 9
#define SBUF (128 * SROW)
#define STGB (4 * SBUF * 2)
#define BUFB (SBUF * 2)

__device__ __forceinline__ void mma_bf16(float* c, const uint32_t* a, const uint32_t* b) {
    asm volatile(
        "mma.sync.aligned.m16n8k16.row.col.f32.bf16.bf16.f32 "
        "{%0,%1,%2,%3}, {%4,%5,%6,%7}, {%8,%9}, {%0,%1,%2,%3};"
        : "+f"(c[0]), "+f"(c[1]), "+f"(c[2]), "+f"(c[3])
        : "r"(a[0]), "r"(a[1]), "r"(a[2]), "r"(a[3]), "r"(b[0]), "r"(b[1]));
}

#define LDSM4(r, a) \
    asm volatile("ldmatrix.sync.aligned.m8n8.x4.shared.b16 {%0,%1,%2,%3}, [%4];" \
        : "=r"((r)[0]), "=r"((r)[1]), "=r"((r)[2]), "=r"((r)[3]) : "r"(a))

__device__ __forceinline__ void cp16(uint32_t saddr, const void* g, bool pred) {
    int sz = pred ? 16 : 0;
    asm volatile("cp.async.cg.shared.global [%0], [%1], 16, %2;"
                 :: "r"(saddr), "l"(g), "r"(sz));
}

__global__ __launch_bounds__(256, 1) void mma_gemm_kernel(int layer,
                                                          const float* __restrict__ bias,
                                                          int relu) {
    extern __shared__ __nv_bfloat16 sm[];

    const int tid = threadIdx.x;
    const int wid = tid >> 5, lane = tid & 31;
    const int m0 = blockIdx.x * 128;
    const int m0w = (wid >> 2) * 64;
    const int n0w = (wid & 3) * 32;
    const int r = lane >> 2, q = lane & 3;

    const uint4* pAH = (const uint4*)g_Ah;
    const uint4* pAL = (const uint4*)g_Al;
    const uint4* pWH = (const uint4*)(g_Wh + (size_t)layer * DIMV * KTOT);
    const uint4* pWL = (const uint4*)(g_Wl + (size_t)layer * DIMV * KTOT);

    uint32_t sbase = (uint32_t)__cvta_generic_to_shared(sm);

    uint32_t aoff[4];
    #pragma unroll
    for (int mt = 0; mt < 4; mt++)
        aoff[mt] = (uint32_t)(m0w + mt * 16 + (lane & 15)) * SROWB + ((lane >> 4) << 4);
    uint32_t boff[2];
    #pragma unroll
    for (int p = 0; p < 2; p++)
        boff[p] = (uint32_t)(n0w + (2 * p + ((lane >> 4) & 1)) * 8 + (lane & 7)) * SROWB
                  + (((lane >> 3) & 1) << 4);

    float acc[4][4][4];
    #pragma unroll
    for (int i = 0; i < 4; i++)
        #pragma unroll
        for (int j = 0; j < 4; j++)
            #pragma unroll
            for (int k = 0; k < 4; k++) acc[i][j][k] = 0.f;

    auto stage_load = [&](int c, int s) {
        const int kb = c * 8;
        uint32_t st = sbase + (uint32_t)s * STGB;
        #pragma unroll
        for (int j = 0; j < 4; j++) {
            int idx = tid + j * 256;
            int row = idx >> 3, col = idx & 7;
            uint32_t so = (uint32_t)(row * SROW4 + col) * 16;
            int m = m0 + row;
            bool ok = m < N2;
            size_t ga = (size_t)(ok ? m : 0) * 80 + kb + col;
            cp16(st + so, pAH + ga, ok);
            cp16(st + BUFB + so, pAL + ga, ok);
            size_t wo = (size_t)row * 80 + kb + col;
            cp16(st + 2 * BUFB + so, pWH + wo, true);
            cp16(st + 3 * BUFB + so, pWL + wo, true);
        }
        asm volatile("cp.async.commit_group;");
    };

    stage_load(0, 0);
    for (int c = 0; c < KTOT / KC; c++) {
        if (c < KTOT / KC - 1) {
            stage_load(c + 1, (c + 1) & 1);
            asm volatile("cp.async.wait_group 1;");
        } else {
            asm volatile("cp.async.wait_group 0;");
        }
        __syncthreads();

        uint32_t bufb = sbase + (uint32_t)(c & 1) * STGB;

        #pragma unroll
        for (int kk = 0; kk < KC; kk += 16) {
            const uint32_t kbyte = (uint32_t)kk * 2;
            uint32_t ah[4][4], al[4][4], bhl[2][4], bll[2][4];
            #pragma unroll
            for (int mt = 0; mt < 4; mt++) {
                LDSM4(ah[mt], bufb + aoff[mt] + kbyte);
                LDSM4(al[mt], bufb + BUFB + aoff[mt] + kbyte);
            }
            #pragma unroll
            for (int p = 0; p < 2; p++) {
                LDSM4(bhl[p], bufb + 2 * BUFB + boff[p] + kbyte);
                LDSM4(bll[p], bufb + 3 * BUFB + boff[p] + kbyte);
            }
            #pragma unroll
            for (int mt = 0; mt < 4; mt++)
                #pragma unroll
                for (int nt = 0; nt < 4; nt++) {
                    const uint32_t* bh = &bhl[nt >> 1][(nt & 1) * 2];
                    const uint32_t* bl = &bll[nt >> 1][(nt & 1) * 2];
                    mma_bf16(acc[mt][nt], ah[mt], bh);
                    mma_bf16(acc[mt][nt], ah[mt], bl);
                    mma_bf16(acc[mt][nt], al[mt], bh);
                }
        }
        __syncthreads();
    }

    // epilogue: layer 0 -> fp32+relu into g_xa; layer 1 -> bf16 hi/lo split
    #pragma unroll
    for (int nt = 0; nt < 4; nt++) {
        int col = n0w + nt * 8 + q * 2;
        float b0 = bias[col], b1 = bias[col + 1];
        #pragma unroll
        for (int mt = 0; mt < 4; mt++) {
            int row = m0 + m0w + mt * 16 + r;
            float v00 = acc[mt][nt][0] + b0, v01 = acc[mt][nt][1] + b1;
            float v10 = acc[mt][nt][2] + b0, v11 = acc[mt][nt][3] + b1;
            if (relu) {
                v00 = fmaxf(v00, 0.f); v01 = fmaxf(v01, 0.f);
                v10 = fmaxf(v10, 0.f); v11 = fmaxf(v11, 0.f);
            }
            if (layer == 0) {
                if (row < N2)
                    *(float2*)(g_xa + (size_t)row * DIMV + col) = make_float2(v00, v01);
                if (row + 8 < N2)
                    *(float2*)(g_xa + (size_t)(row + 8) * DIMV + col) = make_float2(v10, v11);
            } else {
                if (row < N2) {
                    *(uint32_t*)(g_xbh + (size_t)row * DIMV + col) = pack2h(v00, v01);
                    *(uint32_t*)(g_xbl + (size_t)row * DIMV + col) = pack2l(v00, v01);
                }
                if (row + 8 < N2) {
                    *(uint32_t*)(g_xbh + (size_t)(row + 8) * DIMV + col) = pack2h(v10, v11);
                    *(uint32_t*)(g_xbl + (size_t)(row + 8) * DIMV + col) = pack2l(v10, v11);
                }
            }
        }
    }
}

// ---------------- logits: HMMA split-bf16 GEMM + fused softmax ---------------
#define SROWL 136          // smem row stride in bf16 for K=128 tiles
#define SROWL4 17
#define LBUF (128 * SROWL) // bf16 elems per buffer (17408)
#define LBUFB (LBUF * 2)   // bytes per buffer (34816)

__global__ __launch_bounds__(256, 1) void logits_kernel(float* __restrict__ out) {
    extern __shared__ __nv_bfloat16 sm[];

    const int tid = threadIdx.x;
    const int wid = tid >> 5, lane = tid & 31;
    const int m0 = blockIdx.x * 128;
    const int m0w = (wid >> 2) * 64;
    const int n0w = (wid & 3) * 32;
    const int r = lane >> 2, q = lane & 3;

    uint32_t sbase = (uint32_t)__cvta_generic_to_shared(sm);

    const uint4* pAH = (const uint4*)g_xbh;   // 16 uint4 per row
    const uint4* pAL = (const uint4*)g_xbl;
    const uint4* pTH = (const uint4*)g_Th;
    const uint4* pTL = (const uint4*)g_Tl;
    #pragma unroll
    for (int j = 0; j < 8; j++) {
        int idx = tid + j * 256;
        int row = idx >> 4, col = idx & 15;
        uint32_t so = (uint32_t)(row * SROWL4 + col) * 16;
        int m = m0 + row;
        bool ok = m < N2;
        size_t ga = (size_t)(ok ? m : 0) * 16 + col;
        cp16(sbase + so, pAH + ga, ok);
        cp16(sbase + LBUFB + so, pAL + ga, ok);
        size_t ta = (size_t)row * 16 + col;
        cp16(sbase + 2 * LBUFB + so, pTH + ta, true);
        cp16(sbase + 3 * LBUFB + so, pTL + ta, true);
    }
    asm volatile("cp.async.commit_group;");
    asm volatile("cp.async.wait_group 0;");
    __syncthreads();

    float acc[4][4][4];
    #pragma unroll
    for (int i = 0; i < 4; i++)
        #pragma unroll
        for (int j = 0; j < 4; j++)
            #pragma unroll
            for (int k = 0; k < 4; k++) acc[i][j][k] = 0.f;

    const uint32_t* Ah32 = (const uint32_t*)sm;
    const uint32_t* Al32 = (const uint32_t*)(sm + LBUF);
    const uint32_t* Bh32 = (const uint32_t*)(sm + 2 * LBUF);
    const uint32_t* Bl32 = (const uint32_t*)(sm + 3 * LBUF);

    #pragma unroll
    for (int kk = 0; kk < 128; kk += 16) {
        const int kw = kk >> 1;
        uint32_t ah[4][4], al[4][4], bh[4][2], bl[4][2];
        #pragma unroll
        for (int mt = 0; mt < 4; mt++) {
            int row0 = (m0w + mt * 16 + r) * (SROWL / 2);
            int row8 = row0 + 8 * (SROWL / 2);
            ah[mt][0] = Ah32[row0 + kw + q];
            ah[mt][1] = Ah32[row8 + kw + q];
            ah[mt][2] = Ah32[row0 + kw + 4 + q];
            ah[mt][3] = Ah32[row8 + kw + 4 + q];
            al[mt][0] = Al32[row0 + kw + q];
            al[mt][1] = Al32[row8 + kw + q];
            al[mt][2] = Al32[row0 + kw + 4 + q];
            al[mt][3] = Al32[row8 + kw + 4 + q];
        }
        #pragma unroll
        for (int nt = 0; nt < 4; nt++) {
            int nrow = (n0w + nt * 8 + r) * (SROWL / 2);
            bh[nt][0] = Bh32[nrow + kw + q];
            bh[nt][1] = Bh32[nrow + kw + 4 + q];
            bl[nt][0] = Bl32[nrow + kw + q];
            bl[nt][1] = Bl32[nrow + kw + 4 + q];
        }
        #pragma unroll
        for (int mt = 0; mt < 4; mt++)
            #pragma unroll
            for (int nt = 0; nt < 4; nt++) {
                mma_bf16(acc[mt][nt], ah[mt], bh[nt]);
                mma_bf16(acc[mt][nt], ah[mt], bl[nt]);
                mma_bf16(acc[mt][nt], al[mt], bh[nt]);
            }
    }
    __syncthreads();

    // dump logits to smem (reuse staging region), stride 104 floats
    float* LS = (float*)sm;
    #pragma unroll
    for (int nt = 0; nt < 4; nt++) {
        int col = n0w + nt * 8 + q * 2;
        if (col < LCN) {
            #pragma unroll
            for (int mt = 0; mt < 4; mt++) {
                int row = m0w + mt * 16 + r;
                LS[row * 104 + col] = acc[mt][nt][0];
                LS[row * 104 + col + 1] = acc[mt][nt][1];
                LS[(row + 8) * 104 + col] = acc[mt][nt][2];
                LS[(row + 8) * 104 + col + 1] = acc[mt][nt][3];
            }
        }
    }
    __syncthreads();

    // softmax: each warp handles 16 rows
    #pragma unroll 1
    for (int i = 0; i < 16; i++) {
        int row = wid * 16 + i;
        int grow = m0 + row;
        float d0 = LS[row * 104 + lane];
        float d1 = LS[row * 104 + lane + 32];
        float d2 = LS[row * 104 + lane + 64];
        float d3 = (lane < 4) ? LS[row * 104 + lane + 96] : -1e30f;
        float mx = fmaxf(fmaxf(d0, d1), fmaxf(d2, d3));
        #pragma unroll
        for (int off = 16; off > 0; off >>= 1)
            mx = fmaxf(mx, __shfl_xor_sync(0xFFFFFFFFu, mx, off));
        float e0 = expf(d0 - mx), e1 = expf(d1 - mx), e2 = expf(d2 - mx);
        float e3 = (lane < 4) ? expf(d3 - mx) : 0.f;
        float s = e0 + e1 + e2 + e3;
        #pragma unroll
        for (int off = 16; off > 0; off >>= 1)
            s += __shfl_xor_sync(0xFFFFFFFFu, s, off);
        float inv = 1.f / s;
        if (grow < N2) {
            float* orow = out + (size_t)grow * LCN;
            orow[lane] = e0 * inv;
            orow[lane + 32] = e1 * inv;
            orow[lane + 64] = e2 * inv;
            if (lane < 4) orow[lane + 96] = e3 * inv;
        }
    }
}

// ------------------------------- launcher -----------------------------------
extern "C" void kernel_launch(void* const* d_in, const int* in_sizes, int n_in,
                              void* d_out, int out_size) {
    const int* ei2 = (const int*)d_in[0];
    const int* et2 = (const int*)d_in[1];
    const int* ei1 = (const int*)d_in[2];
    const int* lc  = (const int*)d_in[3];
    const float* x0     = (const float*)d_in[4];
    const float* basis1 = (const float*)d_in[5];
    const float* comp1  = (const float*)d_in[6];
    const float* root1  = (const float*)d_in[7];
    const float* bias1  = (const float*)d_in[8];
    const float* basis2 = (const float*)d_in[9];
    const float* comp2  = (const float*)d_in[10];
    const float* root2  = (const float*)d_in[11];
    const float* bias2  = (const float*)d_in[12];
    const float* w      = (const float*)d_in[13];
    float* out = (float*)d_out;

    const int GEMM_SMEM = 2 * STGB;            // 147456 (2 stages)
    cudaFuncSetAttribute(mma_gemm_kernel, cudaFuncAttributeMaxDynamicSharedMemorySize,
                         GEMM_SMEM);
    const int LOGITS_SMEM = 4 * LBUFB;         // 139264
    cudaFuncSetAttribute(logits_kernel, cudaFuncAttributeMaxDynamicSharedMemorySize,
                         LOGITS_SMEM);

    // fork a second stream off the captured stream (graph-capturable pattern)
    cudaStream_t s2;
    cudaStreamCreateWithFlags(&s2, cudaStreamNonBlocking);
    cudaEvent_t evR, evB;
    cudaEventCreateWithFlags(&evR, cudaEventDisableTiming);
    cudaEventCreateWithFlags(&evB, cudaEventDisableTiming);
    cudaEventRecord(evR, 0);
    cudaStreamWaitEvent(s2, evR, 0);

    // chain A (captured stream): graph-1 CSR -> concept -> ty
    zero1_kernel<<<(N1 + 255) / 256, 256>>>();
    hist1_kernel<<<(EDGES / 2 + 255) / 256, 256>>>(ei1);
    scan_g1<<<P1BLKS, 1024>>>();
    scan_add1<<<P1BLKS, 1024>>>();
    scatter1_kernel<<<(EDGES / 2 + 255) / 256, 256>>>(ei1);
    concept_kernel<<<(N2 + 31) / 32, 256>>>((const float4*)x0);
    ty_kernel<<<16, 256>>>((const float4*)x0, lc, (const float4*)w);

    // chain B (stream s2): graph-2 CSR + weight build
    zero2_kernel<<<(N2 * NR + 255) / 256, 256, 0, s2>>>();
    hist2_kernel<<<(EDGES / 2 + 255) / 256, 256, 0, s2>>>(ei2, et2);
    scan_g2<<<P2BLKS, 1024, 0, s2>>>();
    scan_add2<<<P2BLKS, 1024, 0, s2>>>();
    scatter2_kernel<<<(EDGES / 2 + 255) / 256, 256, 0, s2>>>(ei2, et2);
    wbuild_kernel<<<(DIMV * KTOT + 255) / 256, 256, 0, s2>>>(root1, basis1, root2, basis2);

    // join
    cudaEventRecord(evB, s2);
    cudaStreamWaitEvent(0, evB, 0);

    agg_kernel<<<(N2 + 31) / 32, 256>>>(0, comp1);
    mma_gemm_kernel<<<(N2 + 127) / 128, 256, GEMM_SMEM>>>(0, bias1, 1);
    agg_kernel<<<(N2 + 31) / 32, 256>>>(1, comp2);
    mma_gemm_kernel<<<(N2 + 127) / 128, 256, GEMM_SMEM>>>(1, bias2, 0);

    logits_kernel<<<(N2 + 127) / 128, 256, LOGITS_SMEM>>>(out);
}